// round 10
// baseline (speedup 1.0000x reference)
#include <cuda_runtime.h>
#include <cuda_fp16.h>
#include <cstdint>

// Problem constants
#define Bb   4
#define Ss   8192
#define HID  768
#define NH   12
#define HD   64
#define ROWS (Bb*Ss)          // 32768
#define EPS  1e-5f

// ---------------- scratch (device globals; no allocations allowed) ----------
__device__ __half g_Qh[(size_t)ROWS * HID];
__device__ __half g_Kh[(size_t)ROWS * HID];
__device__ __half g_Vh[(size_t)ROWS * HID];
__device__ __half g_Xh[(size_t)ROWS * HID];          // fp16 copy of X
__device__ __half g_Wh[(size_t)3 * HID * HID];       // fp16 [Wq;Wk;Wv]

#define KV_OFF   0                       // 48 * 64 * 64
#define KSUM_OFF (48*4096)               // 48 * 64
#define VSUM_OFF (KSUM_OFF + 48*64)
#define MSUM_OFF (VSUM_OFF + 48*64)
#define RED_TOTAL (MSUM_OFF + 4)
__device__ float g_red[RED_TOTAL];

// ---------------- K0: zero the reduction scratch ----------------------------
__global__ void zero_kernel() {
    int i = blockIdx.x * 256 + threadIdx.x;
    if (i < RED_TOTAL) g_red[i] = 0.0f;
}

// ================= helpers ====================================================
__device__ __forceinline__ uint32_t smem_u32(const void* p) {
    uint32_t a;
    asm("{ .reg .u64 t; cvta.to.shared.u64 t, %1; cvt.u32.u64 %0, t; }" : "=r"(a) : "l"(p));
    return a;
}
#define CP_ASYNC16(dst, src) \
    asm volatile("cp.async.cg.shared.global [%0], [%1], 16;" :: "r"((uint32_t)(dst)), "l"(src) : "memory")
#define CP_COMMIT() asm volatile("cp.async.commit_group;" ::: "memory")
#define SWZ(o) ((o) ^ (((o) >> 3) & 0x70))

__device__ __forceinline__ void mma_f16(float* d, const uint32_t* a, const uint32_t* b) {
    asm volatile(
        "mma.sync.aligned.m16n8k16.row.col.f32.f16.f16.f32 "
        "{%0,%1,%2,%3}, {%4,%5,%6,%7}, {%8,%9}, {%0,%1,%2,%3};"
        : "+f"(d[0]), "+f"(d[1]), "+f"(d[2]), "+f"(d[3])
        : "r"(a[0]), "r"(a[1]), "r"(a[2]), "r"(a[3]), "r"(b[0]), "r"(b[1]));
}
#define LDMATRIX_X4(r, addr) \
    asm volatile("ldmatrix.sync.aligned.m8n8.x4.shared.b16 {%0,%1,%2,%3}, [%4];" \
        : "=r"((r)[0]), "=r"((r)[1]), "=r"((r)[2]), "=r"((r)[3]) : "r"(addr))
#define LDMATRIX_X4_T(r, addr) \
    asm volatile("ldmatrix.sync.aligned.m8n8.x4.trans.shared.b16 {%0,%1,%2,%3}, [%4];" \
        : "=r"((r)[0]), "=r"((r)[1]), "=r"((r)[2]), "=r"((r)[3]) : "r"(addr))
#define ONES2 0x3C003C00u   // half2(1.0, 1.0)

// ---------------- K-1: fp32 -> fp16 converters --------------------------------
__global__ void convX_kernel(const float* __restrict__ X) {
    size_t i = (size_t)blockIdx.x * 256 + threadIdx.x;
    float4 v = ((const float4*)X)[i];
    ((__half2*)g_Xh)[2*i]   = __floats2half2_rn(v.x, v.y);
    ((__half2*)g_Xh)[2*i+1] = __floats2half2_rn(v.z, v.w);
}
__global__ void convW_kernel(const float* __restrict__ Wq,
                             const float* __restrict__ Wk,
                             const float* __restrict__ Wv) {
    size_t i = (size_t)blockIdx.x * 256 + threadIdx.x;
    const size_t per = (size_t)HID * HID / 4;
    const float* src = (i < per) ? Wq : (i < 2*per) ? Wk : Wv;
    size_t j = i % per;
    float4 v = ((const float4*)src)[j];
    ((__half2*)g_Wh)[2*i]   = __floats2half2_rn(v.x, v.y);
    ((__half2*)g_Wh)[2*i+1] = __floats2half2_rn(v.z, v.w);
}

// ---------------- K1: fused QKV projection (fp16 HMMA) + mask + L2-norm -------
// C = X[32768,768] @ W^T. CTA tile 128x128x64, 4 warps (2m x 2n), warp 64x64.
// 3 smem buffers, lookahead-1 cp.async, ONE __syncthreads per k-chunk.
// Each warp's 64 output cols = exactly one head -> warp-local mask+L2 norm.
#define GK_SMEM (6 * 16384)    // A 3x16KB + B 3x16KB

__global__ void __launch_bounds__(128, 2) gemm_qkv_h(
    const float* __restrict__ am,
    const float* __restrict__ bq, const float* __restrict__ bk, const float* __restrict__ bv)
{
    extern __shared__ char smem[];
    const uint32_t sb = smem_u32(smem);

    const int t    = threadIdx.x;
    const int wid  = t >> 5, lane = t & 31;
    const int wm   = wid & 1;           // 2 warps in m
    const int wn   = wid >> 1;          // 2 warps in n
    const int grp  = lane >> 2, tig = lane & 3;

    const int nb = blockIdx.x;          // 0..17
    const int mb = blockIdx.y;          // 0..255
    const int mat = nb / 6;             // 0=q 1=k 2=v
    const float* bias = (mat == 0) ? bq : (mat == 1) ? bk : bv;
    __half* C         = (mat == 0) ? g_Qh : (mat == 1) ? g_Kh : g_Vh;
    const int n0 = (nb % 6) * 128;
    const int m0 = mb * 128;

    const __half* Asrc = g_Xh + (size_t)m0 * 768;
    const __half* Bsrc = g_Wh + (size_t)nb * 128 * 768;

    auto load_tile = [&](int kt, int stg) {
        uint32_t Ad = sb + stg * 16384;
        uint32_t Bd = sb + 49152 + stg * 16384;
        #pragma unroll
        for (int i = 0; i < 8; i++) {
            int s   = t + i * 128;          // 0..1023
            int row = s >> 3, ch = s & 7;
            uint32_t off = SWZ((uint32_t)(row * 128 + ch * 16));
            CP_ASYNC16(Ad + off, Asrc + (size_t)row * 768 + kt * 64 + ch * 8);
            CP_ASYNC16(Bd + off, Bsrc + (size_t)row * 768 + kt * 64 + ch * 8);
        }
        CP_COMMIT();
    };

    float acc[4][8][4];
    #pragma unroll
    for (int i = 0; i < 4; i++)
        #pragma unroll
        for (int j = 0; j < 8; j++)
            #pragma unroll
            for (int c = 0; c < 4; c++) acc[i][j][c] = 0.0f;

    load_tile(0, 0);

    for (int kt = 0; kt < 12; kt++) {
        const int buf = kt % 3;
        if (kt + 1 < 12) {
            load_tile(kt + 1, (kt + 1) % 3);
            asm volatile("cp.async.wait_group 1;" ::: "memory");
        } else {
            asm volatile("cp.async.wait_group 0;" ::: "memory");
        }
        __syncthreads();
        // no trailing sync: next load targets buffer (kt+2)%3, last read at
        // compute(kt-1), which all warps passed before this barrier.

        const uint32_t Abase = sb + buf * 16384;
        const uint32_t Bbase = sb + 49152 + buf * 16384;

        #pragma unroll
        for (int ks = 0; ks < 4; ks++) {
            const int k0b = ks * 32;
            uint32_t afr[4][4];
            #pragma unroll
            for (int mt = 0; mt < 4; mt++) {
                int row = wm * 64 + mt * 16 + (lane & 15);
                LDMATRIX_X4(afr[mt], Abase + SWZ((uint32_t)(row * 128 + k0b + (lane >> 4) * 16)));
            }
            uint32_t bfr[4][4];
            #pragma unroll
            for (int bp = 0; bp < 4; bp++) {
                int row = wn * 64 + bp * 16 + (lane & 7) + ((lane >> 4) << 3);
                LDMATRIX_X4(bfr[bp], Bbase + SWZ((uint32_t)(row * 128 + k0b + ((lane >> 3) & 1) * 16)));
            }
            #pragma unroll
            for (int mt = 0; mt < 4; mt++)
                #pragma unroll
                for (int nt = 0; nt < 8; nt++)
                    mma_f16(acc[mt][nt], afr[mt], &bfr[nt >> 1][(nt & 1) * 2]);
        }
    }

    // -------- epilogue (warp-local: this warp's 64 cols = one head) --------
    const int colbase = n0 + wn * 64;
    float bx[8], by[8];
    #pragma unroll
    for (int nt = 0; nt < 8; nt++) {
        bx[nt] = bias[colbase + nt * 8 + tig * 2];
        by[nt] = bias[colbase + nt * 8 + tig * 2 + 1];
    }

    if (mat < 2) {
        #pragma unroll
        for (int mt = 0; mt < 4; mt++) {
            const int r0 = m0 + wm * 64 + mt * 16 + grp;
            const float mr0 = (am[r0]     != 0.0f) ? 0.0f : 1.0f;
            const float mr1 = (am[r0 + 8] != 0.0f) ? 0.0f : 1.0f;
            float ssq0 = 0.0f, ssq1 = 0.0f;
            #pragma unroll
            for (int nt = 0; nt < 8; nt++) {
                float a0 = (acc[mt][nt][0] + bx[nt]) * mr0;
                float a1 = (acc[mt][nt][1] + by[nt]) * mr0;
                float a2 = (acc[mt][nt][2] + bx[nt]) * mr1;
                float a3 = (acc[mt][nt][3] + by[nt]) * mr1;
                acc[mt][nt][0] = a0; acc[mt][nt][1] = a1;
                acc[mt][nt][2] = a2; acc[mt][nt][3] = a3;
                ssq0 += a0*a0 + a1*a1;
                ssq1 += a2*a2 + a3*a3;
            }
            #pragma unroll
            for (int off = 1; off <= 2; off <<= 1) {
                ssq0 += __shfl_xor_sync(0xffffffffu, ssq0, off);
                ssq1 += __shfl_xor_sync(0xffffffffu, ssq1, off);
            }
            const float inv0 = 1.0f / (sqrtf(ssq0) + EPS);
            const float inv1 = 1.0f / (sqrtf(ssq1) + EPS);
            #pragma unroll
            for (int nt = 0; nt < 8; nt++) {
                size_t gc = (size_t)r0 * 768 + colbase + nt * 8 + tig * 2;
                *(__half2*)&C[gc]           = __floats2half2_rn(acc[mt][nt][0] * inv0, acc[mt][nt][1] * inv0);
                *(__half2*)&C[gc + 8 * 768] = __floats2half2_rn(acc[mt][nt][2] * inv1, acc[mt][nt][3] * inv1);
            }
        }
    } else {
        #pragma unroll
        for (int mt = 0; mt < 4; mt++) {
            const int r0 = m0 + wm * 64 + mt * 16 + grp;
            #pragma unroll
            for (int nt = 0; nt < 8; nt++) {
                size_t gc = (size_t)r0 * 768 + colbase + nt * 8 + tig * 2;
                *(__half2*)&C[gc]           = __floats2half2_rn(acc[mt][nt][0] + bx[nt], acc[mt][nt][1] + by[nt]);
                *(__half2*)&C[gc + 8 * 768] = __floats2half2_rn(acc[mt][nt][2] + bx[nt], acc[mt][nt][3] + by[nt]);
            }
        }
    }
}

// ---------------- K2b: msum per batch ----------------------------------------
__global__ void msum_kernel(const float* __restrict__ am) {
    __shared__ float red[256];
    int b = blockIdx.x;
    float s = 0.0f;
    for (int i = threadIdx.x; i < Ss; i += 256)
        s += (am[b * Ss + i] != 0.0f) ? 0.0f : 1.0f;
    red[threadIdx.x] = s;
    __syncthreads();
    for (int o = 128; o; o >>= 1) {
        if (threadIdx.x < o) red[threadIdx.x] += red[threadIdx.x + o];
        __syncthreads();
    }
    if (threadIdx.x == 0) g_red[MSUM_OFF + b] = red[0];
}

// ---------------- K3: kv = K^T V (+ ksum, vsum) via HMMA ----------------------
__global__ void __launch_bounds__(160) kv_mma() {
    __shared__ __half Ks[2][64 * 64];
    __shared__ __half Vs[2][64 * 64];

    const int bh = blockIdx.x, sc = blockIdx.y;
    const int b = bh / NH, h = bh % NH;
    const int t = threadIdx.x;
    const int wid = t >> 5, lane = t & 31;
    const int grp = lane >> 2, tig = lane & 3;
    const uint32_t sK = smem_u32(Ks);
    const uint32_t sV = smem_u32(Vs);
    const int s_base = sc * 512;

    auto load_tile = [&](int tile, int buf) {
        int s0 = s_base + tile * 64;
        for (int i = t; i < 1024; i += 160) {
            int isV = i >> 9;
            int j = i & 511;
            int row = j >> 3, ch = j & 7;
            uint32_t off = SWZ((uint32_t)(row * 128 + ch * 16));
            const __half* src = (isV ? g_Vh : g_Kh)
                + ((size_t)(b * Ss + s0 + row)) * 768 + h * 64 + ch * 8;
            CP_ASYNC16((isV ? sV : sK) + buf * 8192 + off, src);
        }
        CP_COMMIT();
    };

    float acc[9][4];
    #pragma unroll
    for (int j = 0; j < 9; j++)
        #pragma unroll
        for (int c = 0; c < 4; c++) acc[j][c] = 0.0f;

    uint32_t a_ones[4];
    a_ones[0] = (grp == 0) ? ONES2 : 0u;
    a_ones[1] = 0u;
    a_ones[2] = (grp == 0) ? ONES2 : 0u;
    a_ones[3] = 0u;
    uint32_t b_ones[2];
    b_ones[0] = (grp == 0) ? ONES2 : 0u;
    b_ones[1] = (grp == 0) ? ONES2 : 0u;

    load_tile(0, 0);

    for (int tile = 0; tile < 8; tile++) {
        const int buf = tile & 1;
        if (tile + 1 < 8) {
            load_tile(tile + 1, buf ^ 1);
            asm volatile("cp.async.wait_group 1;" ::: "memory");
        } else {
            asm volatile("cp.async.wait_group 0;" ::: "memory");
        }
        __syncthreads();

        const uint32_t Kb = sK + buf * 8192;
        const uint32_t Vb = sV + buf * 8192;

        #pragma unroll
        for (int ks = 0; ks < 4; ks++) {
            uint32_t afr[4];
            if (wid < 4) {
                int row = ks * 16 + ((lane >> 4) << 3) + (lane & 7);
                LDMATRIX_X4_T(afr, Kb + SWZ((uint32_t)(row * 128 + wid * 32 + ((lane >> 3) & 1) * 16)));
            } else {
                afr[0] = a_ones[0]; afr[1] = a_ones[1];
                afr[2] = a_ones[2]; afr[3] = a_ones[3];
            }
            uint32_t bfr[4][4];
            #pragma unroll
            for (int bp = 0; bp < 4; bp++) {
                int row = ks * 16 + (((lane >> 3) & 1) << 3) + (lane & 7);
                LDMATRIX_X4_T(bfr[bp], Vb + SWZ((uint32_t)(row * 128 + bp * 32 + (lane >> 4) * 16)));
            }
            #pragma unroll
            for (int nt = 0; nt < 8; nt++)
                mma_f16(acc[nt], afr, &bfr[nt >> 1][(nt & 1) * 2]);
            mma_f16(acc[8], afr, b_ones);
        }
        __syncthreads();
    }

    float* kvb = g_red + KV_OFF + bh * 4096;
    if (wid < 4) {
        int d = wid * 16 + grp;
        #pragma unroll
        for (int nt = 0; nt < 8; nt++) {
            int e = nt * 8 + tig * 2;
            atomicAdd(&kvb[d * 64 + e],           acc[nt][0]);
            atomicAdd(&kvb[d * 64 + e + 1],       acc[nt][1]);
            atomicAdd(&kvb[(d + 8) * 64 + e],     acc[nt][2]);
            atomicAdd(&kvb[(d + 8) * 64 + e + 1], acc[nt][3]);
        }
        if (tig == 0) {
            atomicAdd(&g_red[KSUM_OFF + bh * 64 + d],     acc[8][0]);
            atomicAdd(&g_red[KSUM_OFF + bh * 64 + d + 8], acc[8][2]);
        }
    } else if (grp == 0) {
        #pragma unroll
        for (int nt = 0; nt < 8; nt++) {
            int e = nt * 8 + tig * 2;
            atomicAdd(&g_red[VSUM_OFF + bh * 64 + e],     acc[nt][0]);
            atomicAdd(&g_red[VSUM_OFF + bh * 64 + e + 1], acc[nt][1]);
        }
    }
}

// ---------------- K4: out via fp16 HMMA, 4 q-tiles per CTA --------------------
// Grid (48, 16): CTA covers 512 s-rows of one (b,h); kvT/vsum built once.
__global__ void __launch_bounds__(128) out_mma(float* __restrict__ out) {
    __shared__ __half Qs[2][128 * 64];
    __shared__ __half kvT[80 * 64];
    __shared__ float nqs[128];
    __shared__ float vsm[64];

    const int bh = blockIdx.x, sc = blockIdx.y;
    const int b = bh / NH, h = bh % NH;
    const int t = threadIdx.x;
    const int wid = t >> 5, lane = t & 31;
    const int grp = lane >> 2, tig = lane & 3;
    const uint32_t sQ = smem_u32(Qs);
    const uint32_t sT = smem_u32(kvT);

    auto load_q = [&](int st2, int buf) {
        int s0 = sc * 512 + st2 * 128;
        #pragma unroll
        for (int i = 0; i < 8; i++) {
            int s = t + i * 128;
            int row = s >> 3, ch = s & 7;
            CP_ASYNC16(sQ + buf * 16384 + SWZ((uint32_t)(row * 128 + ch * 16)),
                       g_Qh + ((size_t)(b * Ss + s0 + row)) * 768 + h * 64 + ch * 8);
        }
        CP_COMMIT();
    };

    load_q(0, 0);

    // build kvT once (transposed kv + ksum row + zero rows)
    for (int idx = t; idx < 80 * 64; idx += 128) {
        int n = idx >> 6, k = idx & 63;
        float v;
        if (n < 64)       v = g_red[KV_OFF + bh * 4096 + k * 64 + n];
        else if (n == 64) v = g_red[KSUM_OFF + bh * 64 + k];
        else              v = 0.0f;
        *(__half*)((char*)kvT + SWZ((uint32_t)(n * 128 + k * 2))) = __float2half_rn(v);
    }
    if (t < 64) vsm[t] = g_red[VSUM_OFF + bh * 64 + t];
    const float msum = g_red[MSUM_OFF + b];

    for (int st2 = 0; st2 < 4; st2++) {
        const int buf = st2 & 1;
        if (st2 + 1 < 4) {
            load_q(st2 + 1, buf ^ 1);
            asm volatile("cp.async.wait_group 1;" ::: "memory");
        } else {
            asm volatile("cp.async.wait_group 0;" ::: "memory");
        }
        __syncthreads();   // Q(st2) visible; prior iter's nqs reads complete

        const uint32_t Qb = sQ + buf * 16384;

        float acc[2][9][4];
        #pragma unroll
        for (int i = 0; i < 2; i++)
            #pragma unroll
            for (int j = 0; j < 9; j++)
                #pragma unroll
                for (int c = 0; c < 4; c++) acc[i][j][c] = 0.0f;

        #pragma unroll
        for (int ks = 0; ks < 4; ks++) {
            const int k0b = ks * 32;
            uint32_t afr[2][4];
            #pragma unroll
            for (int mt = 0; mt < 2; mt++) {
                int row = wid * 32 + mt * 16 + (lane & 15);
                LDMATRIX_X4(afr[mt], Qb + SWZ((uint32_t)(row * 128 + k0b + (lane >> 4) * 16)));
            }
            uint32_t bfr[5][4];
            #pragma unroll
            for (int bp = 0; bp < 5; bp++) {
                int row = bp * 16 + (lane & 7) + ((lane >> 4) << 3);
                LDMATRIX_X4(bfr[bp], sT + SWZ((uint32_t)(row * 128 + k0b + ((lane >> 3) & 1) * 16)));
            }
            #pragma unroll
            for (int mt = 0; mt < 2; mt++)
                #pragma unroll
                for (int nt = 0; nt < 9; nt++)
                    mma_f16(acc[mt][nt], afr[mt], &bfr[nt >> 1][(nt & 1) * 2]);
        }

        if (tig == 0) {
            #pragma unroll
            for (int mt = 0; mt < 2; mt++) {
                nqs[wid * 32 + mt * 16 + grp]     = acc[mt][8][0];
                nqs[wid * 32 + mt * 16 + grp + 8] = acc[mt][8][2];
            }
        }
        __syncthreads();

        const int srow = sc * 512 + st2 * 128;
        #pragma unroll
        for (int mt = 0; mt < 2; mt++) {
            int r0 = wid * 32 + mt * 16 + grp;
            float inv0 = 1.0f / (nqs[r0]     + EPS + msum);
            float inv1 = 1.0f / (nqs[r0 + 8] + EPS + msum);
            size_t g0 = ((size_t)(b * Ss + srow + r0))     * HID + h * HD;
            size_t g1 = ((size_t)(b * Ss + srow + r0 + 8)) * HID + h * HD;
            #pragma unroll
            for (int nt = 0; nt < 8; nt++) {
                int col = nt * 8 + tig * 2;
                float vx = vsm[col], vy = vsm[col + 1];
                float2 o0 = make_float2((acc[mt][nt][0] + vx) * inv0, (acc[mt][nt][1] + vy) * inv0);
                float2 o1 = make_float2((acc[mt][nt][2] + vx) * inv1, (acc[mt][nt][3] + vy) * inv1);
                *(float2*)&out[g0 + col] = o0;
                *(float2*)&out[g1 + col] = o1;
            }
        }
    }
}

// ---------------- launch ------------------------------------------------------
extern "C" void kernel_launch(void* const* d_in, const int* in_sizes, int n_in,
                              void* d_out, int out_size)
{
    const float* X  = (const float*)d_in[0];
    const float* am = (const float*)d_in[1];
    const float* Wq = (const float*)d_in[2];
    const float* bq = (const float*)d_in[3];
    const float* Wk = (const float*)d_in[4];
    const float* bk = (const float*)d_in[5];
    const float* Wv = (const float*)d_in[6];
    const float* bv = (const float*)d_in[7];
    float* out = (float*)d_out;

    cudaFuncSetAttribute(gemm_qkv_h, cudaFuncAttributeMaxDynamicSharedMemorySize, GK_SMEM);

    // gemm stays the 4th launch for ncu capture; msum only feeds out_mma.
    zero_kernel<<<(RED_TOTAL + 255) / 256, 256>>>();                       // 1
    convX_kernel<<<(ROWS * HID / 4) / 256, 256>>>(X);                      // 2
    convW_kernel<<<(3 * HID * HID / 4) / 256, 256>>>(Wq, Wk, Wv);          // 3

    dim3 g1(18, 256);
    gemm_qkv_h<<<g1, 128, GK_SMEM>>>(am, bq, bk, bv);                      // 4

    msum_kernel<<<Bb, 256>>>(am);                                          // 5

    dim3 g3(48, 16);
    kv_mma<<<g3, 160>>>();                                                 // 6

    dim3 g4(48, 16);
    out_mma<<<g4, 128>>>(out);                                             // 7
}

// round 11
// speedup vs baseline: 1.4493x; 1.4493x over previous
#include <cuda_runtime.h>
#include <cuda_fp16.h>
#include <cstdint>

// Problem constants
#define Bb   4
#define Ss   8192
#define HID  768
#define NH   12
#define HD   64
#define ROWS (Bb*Ss)          // 32768
#define EPS  1e-5f

// ---------------- scratch (device globals; no allocations allowed) ----------
__device__ __half g_Qh[(size_t)ROWS * HID];
__device__ __half g_Kh[(size_t)ROWS * HID];
__device__ __half g_Vh[(size_t)ROWS * HID];
__device__ __half g_Xh[(size_t)ROWS * HID];          // fp16 copy of X
__device__ __half g_Wh[(size_t)3 * HID * HID];       // fp16 [Wq;Wk;Wv]

#define KV_OFF   0                       // 48 * 64 * 64
#define KSUM_OFF (48*4096)               // 48 * 64
#define VSUM_OFF (KSUM_OFF + 48*64)
#define MSUM_OFF (VSUM_OFF + 48*64)
#define RED_TOTAL (MSUM_OFF + 4)
__device__ float g_red[RED_TOTAL];

// ---------------- K0: zero the reduction scratch ----------------------------
__global__ void zero_kernel() {
    int i = blockIdx.x * 256 + threadIdx.x;
    if (i < RED_TOTAL) g_red[i] = 0.0f;
}

// ================= helpers ====================================================
__device__ __forceinline__ uint32_t smem_u32(const void* p) {
    uint32_t a;
    asm("{ .reg .u64 t; cvta.to.shared.u64 t, %1; cvt.u32.u64 %0, t; }" : "=r"(a) : "l"(p));
    return a;
}
#define CP_ASYNC16(dst, src) \
    asm volatile("cp.async.cg.shared.global [%0], [%1], 16;" :: "r"((uint32_t)(dst)), "l"(src) : "memory")
#define CP_COMMIT() asm volatile("cp.async.commit_group;" ::: "memory")
#define SWZ(o) ((o) ^ (((o) >> 3) & 0x70))

__device__ __forceinline__ void mma_f16(float* d, const uint32_t* a, const uint32_t* b) {
    asm volatile(
        "mma.sync.aligned.m16n8k16.row.col.f32.f16.f16.f32 "
        "{%0,%1,%2,%3}, {%4,%5,%6,%7}, {%8,%9}, {%0,%1,%2,%3};"
        : "+f"(d[0]), "+f"(d[1]), "+f"(d[2]), "+f"(d[3])
        : "r"(a[0]), "r"(a[1]), "r"(a[2]), "r"(a[3]), "r"(b[0]), "r"(b[1]));
}
#define LDMATRIX_X4(r, addr) \
    asm volatile("ldmatrix.sync.aligned.m8n8.x4.shared.b16 {%0,%1,%2,%3}, [%4];" \
        : "=r"((r)[0]), "=r"((r)[1]), "=r"((r)[2]), "=r"((r)[3]) : "r"(addr))
#define LDMATRIX_X4_T(r, addr) \
    asm volatile("ldmatrix.sync.aligned.m8n8.x4.trans.shared.b16 {%0,%1,%2,%3}, [%4];" \
        : "=r"((r)[0]), "=r"((r)[1]), "=r"((r)[2]), "=r"((r)[3]) : "r"(addr))
#define ONES2 0x3C003C00u   // half2(1.0, 1.0)

// ---------------- K-1: fp32 -> fp16 converters --------------------------------
__global__ void convX_kernel(const float* __restrict__ X) {
    size_t i = (size_t)blockIdx.x * 256 + threadIdx.x;
    float4 v = ((const float4*)X)[i];
    ((__half2*)g_Xh)[2*i]   = __floats2half2_rn(v.x, v.y);
    ((__half2*)g_Xh)[2*i+1] = __floats2half2_rn(v.z, v.w);
}
__global__ void convW_kernel(const float* __restrict__ Wq,
                             const float* __restrict__ Wk,
                             const float* __restrict__ Wv) {
    size_t i = (size_t)blockIdx.x * 256 + threadIdx.x;
    const size_t per = (size_t)HID * HID / 4;
    const float* src = (i < per) ? Wq : (i < 2*per) ? Wk : Wv;
    size_t j = i % per;
    float4 v = ((const float4*)src)[j];
    ((__half2*)g_Wh)[2*i]   = __floats2half2_rn(v.x, v.y);
    ((__half2*)g_Wh)[2*i+1] = __floats2half2_rn(v.z, v.w);
}

// ---------------- K1: fused QKV projection (fp16 HMMA) + mask + L2-norm -------
// C = X[32768,768] @ W^T. CTA tile 128x128x64, 4 warps (2m x 2n), warp 64x64.
// 3 smem stages; per-iter: wait(load kt) -> sync -> prefetch(kt+2) -> compute.
// Each warp's 64 output cols = exactly one head -> warp-local mask+L2 norm.
#define GK_SMEM (6 * 16384)    // A 3x16KB + B 3x16KB

__global__ void __launch_bounds__(128, 2) gemm_qkv_h(
    const float* __restrict__ am,
    const float* __restrict__ bq, const float* __restrict__ bk, const float* __restrict__ bv)
{
    extern __shared__ char smem[];
    const uint32_t sb = smem_u32(smem);

    const int t    = threadIdx.x;
    const int wid  = t >> 5, lane = t & 31;
    const int wm   = wid & 1;           // 2 warps in m
    const int wn   = wid >> 1;          // 2 warps in n
    const int grp  = lane >> 2, tig = lane & 3;

    const int nb = blockIdx.x;          // 0..17
    const int mb = blockIdx.y;          // 0..255
    const int mat = nb / 6;             // 0=q 1=k 2=v
    const float* bias = (mat == 0) ? bq : (mat == 1) ? bk : bv;
    __half* C         = (mat == 0) ? g_Qh : (mat == 1) ? g_Kh : g_Vh;
    const int n0 = (nb % 6) * 128;
    const int m0 = mb * 128;

    const __half* Asrc = g_Xh + (size_t)m0 * 768;
    const __half* Bsrc = g_Wh + (size_t)nb * 128 * 768;

    auto load_tile = [&](int kt, int stg) {
        uint32_t Ad = sb + stg * 16384;
        uint32_t Bd = sb + 49152 + stg * 16384;
        #pragma unroll
        for (int i = 0; i < 8; i++) {
            int s   = t + i * 128;          // 0..1023
            int row = s >> 3, ch = s & 7;
            uint32_t off = SWZ((uint32_t)(row * 128 + ch * 16));
            CP_ASYNC16(Ad + off, Asrc + (size_t)row * 768 + kt * 64 + ch * 8);
            CP_ASYNC16(Bd + off, Bsrc + (size_t)row * 768 + kt * 64 + ch * 8);
        }
        CP_COMMIT();
    };

    float acc[4][8][4];
    #pragma unroll
    for (int i = 0; i < 4; i++)
        #pragma unroll
        for (int j = 0; j < 8; j++)
            #pragma unroll
            for (int c = 0; c < 4; c++) acc[i][j][c] = 0.0f;

    load_tile(0, 0);
    load_tile(1, 1);

    for (int kt = 0; kt < 12; kt++) {
        const int buf = kt % 3;
        // load(kt) must be complete; load(kt+1) may remain in flight
        if (kt < 11) asm volatile("cp.async.wait_group 1;" ::: "memory");
        else         asm volatile("cp.async.wait_group 0;" ::: "memory");
        __syncthreads();   // everyone's load(kt) visible + compute(kt-1) done
        // prefetch kt+2 into stage (kt+2)%3 == (kt-1)%3, freed by the barrier
        if (kt + 2 < 12) load_tile(kt + 2, (kt + 2) % 3);

        const uint32_t Abase = sb + buf * 16384;
        const uint32_t Bbase = sb + 49152 + buf * 16384;

        #pragma unroll
        for (int ks = 0; ks < 4; ks++) {
            const int k0b = ks * 32;
            uint32_t afr[4][4];
            #pragma unroll
            for (int mt = 0; mt < 4; mt++) {
                int row = wm * 64 + mt * 16 + (lane & 15);
                LDMATRIX_X4(afr[mt], Abase + SWZ((uint32_t)(row * 128 + k0b + (lane >> 4) * 16)));
            }
            uint32_t bfr[4][4];
            #pragma unroll
            for (int bp = 0; bp < 4; bp++) {
                int row = wn * 64 + bp * 16 + (lane & 7) + ((lane >> 4) << 3);
                LDMATRIX_X4(bfr[bp], Bbase + SWZ((uint32_t)(row * 128 + k0b + ((lane >> 3) & 1) * 16)));
            }
            #pragma unroll
            for (int mt = 0; mt < 4; mt++)
                #pragma unroll
                for (int nt = 0; nt < 8; nt++)
                    mma_f16(acc[mt][nt], afr[mt], &bfr[nt >> 1][(nt & 1) * 2]);
        }
    }

    // -------- epilogue (warp-local: this warp's 64 cols = one head) --------
    const int colbase = n0 + wn * 64;
    float bx[8], by[8];
    #pragma unroll
    for (int nt = 0; nt < 8; nt++) {
        bx[nt] = bias[colbase + nt * 8 + tig * 2];
        by[nt] = bias[colbase + nt * 8 + tig * 2 + 1];
    }

    if (mat < 2) {
        #pragma unroll
        for (int mt = 0; mt < 4; mt++) {
            const int r0 = m0 + wm * 64 + mt * 16 + grp;
            const float mr0 = (am[r0]     != 0.0f) ? 0.0f : 1.0f;
            const float mr1 = (am[r0 + 8] != 0.0f) ? 0.0f : 1.0f;
            float ssq0 = 0.0f, ssq1 = 0.0f;
            #pragma unroll
            for (int nt = 0; nt < 8; nt++) {
                float a0 = (acc[mt][nt][0] + bx[nt]) * mr0;
                float a1 = (acc[mt][nt][1] + by[nt]) * mr0;
                float a2 = (acc[mt][nt][2] + bx[nt]) * mr1;
                float a3 = (acc[mt][nt][3] + by[nt]) * mr1;
                acc[mt][nt][0] = a0; acc[mt][nt][1] = a1;
                acc[mt][nt][2] = a2; acc[mt][nt][3] = a3;
                ssq0 += a0*a0 + a1*a1;
                ssq1 += a2*a2 + a3*a3;
            }
            #pragma unroll
            for (int off = 1; off <= 2; off <<= 1) {
                ssq0 += __shfl_xor_sync(0xffffffffu, ssq0, off);
                ssq1 += __shfl_xor_sync(0xffffffffu, ssq1, off);
            }
            const float inv0 = 1.0f / (sqrtf(ssq0) + EPS);
            const float inv1 = 1.0f / (sqrtf(ssq1) + EPS);
            #pragma unroll
            for (int nt = 0; nt < 8; nt++) {
                size_t gc = (size_t)r0 * 768 + colbase + nt * 8 + tig * 2;
                *(__half2*)&C[gc]           = __floats2half2_rn(acc[mt][nt][0] * inv0, acc[mt][nt][1] * inv0);
                *(__half2*)&C[gc + 8 * 768] = __floats2half2_rn(acc[mt][nt][2] * inv1, acc[mt][nt][3] * inv1);
            }
        }
    } else {
        #pragma unroll
        for (int mt = 0; mt < 4; mt++) {
            const int r0 = m0 + wm * 64 + mt * 16 + grp;
            #pragma unroll
            for (int nt = 0; nt < 8; nt++) {
                size_t gc = (size_t)r0 * 768 + colbase + nt * 8 + tig * 2;
                *(__half2*)&C[gc]           = __floats2half2_rn(acc[mt][nt][0] + bx[nt], acc[mt][nt][1] + by[nt]);
                *(__half2*)&C[gc + 8 * 768] = __floats2half2_rn(acc[mt][nt][2] + bx[nt], acc[mt][nt][3] + by[nt]);
            }
        }
    }
}

// ---------------- K2b: msum per batch ----------------------------------------
__global__ void msum_kernel(const float* __restrict__ am) {
    __shared__ float red[256];
    int b = blockIdx.x;
    float s = 0.0f;
    for (int i = threadIdx.x; i < Ss; i += 256)
        s += (am[b * Ss + i] != 0.0f) ? 0.0f : 1.0f;
    red[threadIdx.x] = s;
    __syncthreads();
    for (int o = 128; o; o >>= 1) {
        if (threadIdx.x < o) red[threadIdx.x] += red[threadIdx.x + o];
        __syncthreads();
    }
    if (threadIdx.x == 0) g_red[MSUM_OFF + b] = red[0];
}

// ---------------- K3: kv = K^T V (+ ksum, vsum) via HMMA ----------------------
__global__ void __launch_bounds__(160) kv_mma() {
    __shared__ __half Ks[2][64 * 64];
    __shared__ __half Vs[2][64 * 64];

    const int bh = blockIdx.x, sc = blockIdx.y;
    const int b = bh / NH, h = bh % NH;
    const int t = threadIdx.x;
    const int wid = t >> 5, lane = t & 31;
    const int grp = lane >> 2, tig = lane & 3;
    const uint32_t sK = smem_u32(Ks);
    const uint32_t sV = smem_u32(Vs);
    const int s_base = sc * 512;

    auto load_tile = [&](int tile, int buf) {
        int s0 = s_base + tile * 64;
        for (int i = t; i < 1024; i += 160) {
            int isV = i >> 9;
            int j = i & 511;
            int row = j >> 3, ch = j & 7;
            uint32_t off = SWZ((uint32_t)(row * 128 + ch * 16));
            const __half* src = (isV ? g_Vh : g_Kh)
                + ((size_t)(b * Ss + s0 + row)) * 768 + h * 64 + ch * 8;
            CP_ASYNC16((isV ? sV : sK) + buf * 8192 + off, src);
        }
        CP_COMMIT();
    };

    float acc[9][4];
    #pragma unroll
    for (int j = 0; j < 9; j++)
        #pragma unroll
        for (int c = 0; c < 4; c++) acc[j][c] = 0.0f;

    uint32_t a_ones[4];
    a_ones[0] = (grp == 0) ? ONES2 : 0u;
    a_ones[1] = 0u;
    a_ones[2] = (grp == 0) ? ONES2 : 0u;
    a_ones[3] = 0u;
    uint32_t b_ones[2];
    b_ones[0] = (grp == 0) ? ONES2 : 0u;
    b_ones[1] = (grp == 0) ? ONES2 : 0u;

    load_tile(0, 0);

    for (int tile = 0; tile < 8; tile++) {
        const int buf = tile & 1;
        if (tile + 1 < 8) {
            load_tile(tile + 1, buf ^ 1);
            asm volatile("cp.async.wait_group 1;" ::: "memory");
        } else {
            asm volatile("cp.async.wait_group 0;" ::: "memory");
        }
        __syncthreads();

        const uint32_t Kb = sK + buf * 8192;
        const uint32_t Vb = sV + buf * 8192;

        #pragma unroll
        for (int ks = 0; ks < 4; ks++) {
            uint32_t afr[4];
            if (wid < 4) {
                int row = ks * 16 + ((lane >> 4) << 3) + (lane & 7);
                LDMATRIX_X4_T(afr, Kb + SWZ((uint32_t)(row * 128 + wid * 32 + ((lane >> 3) & 1) * 16)));
            } else {
                afr[0] = a_ones[0]; afr[1] = a_ones[1];
                afr[2] = a_ones[2]; afr[3] = a_ones[3];
            }
            uint32_t bfr[4][4];
            #pragma unroll
            for (int bp = 0; bp < 4; bp++) {
                int row = ks * 16 + (((lane >> 3) & 1) << 3) + (lane & 7);
                LDMATRIX_X4_T(bfr[bp], Vb + SWZ((uint32_t)(row * 128 + bp * 32 + (lane >> 4) * 16)));
            }
            #pragma unroll
            for (int nt = 0; nt < 8; nt++)
                mma_f16(acc[nt], afr, &bfr[nt >> 1][(nt & 1) * 2]);
            mma_f16(acc[8], afr, b_ones);
        }
        __syncthreads();
    }

    float* kvb = g_red + KV_OFF + bh * 4096;
    if (wid < 4) {
        int d = wid * 16 + grp;
        #pragma unroll
        for (int nt = 0; nt < 8; nt++) {
            int e = nt * 8 + tig * 2;
            atomicAdd(&kvb[d * 64 + e],           acc[nt][0]);
            atomicAdd(&kvb[d * 64 + e + 1],       acc[nt][1]);
            atomicAdd(&kvb[(d + 8) * 64 + e],     acc[nt][2]);
            atomicAdd(&kvb[(d + 8) * 64 + e + 1], acc[nt][3]);
        }
        if (tig == 0) {
            atomicAdd(&g_red[KSUM_OFF + bh * 64 + d],     acc[8][0]);
            atomicAdd(&g_red[KSUM_OFF + bh * 64 + d + 8], acc[8][2]);
        }
    } else if (grp == 0) {
        #pragma unroll
        for (int nt = 0; nt < 8; nt++) {
            int e = nt * 8 + tig * 2;
            atomicAdd(&g_red[VSUM_OFF + bh * 64 + e],     acc[nt][0]);
            atomicAdd(&g_red[VSUM_OFF + bh * 64 + e + 1], acc[nt][1]);
        }
    }
}

// ---------------- K4: out via fp16 HMMA, 4 q-tiles per CTA --------------------
// Grid (48, 16): CTA covers 512 s-rows of one (b,h); kvT/vsum built once.
__global__ void __launch_bounds__(128) out_mma(float* __restrict__ out) {
    __shared__ __half Qs[2][128 * 64];
    __shared__ __half kvT[80 * 64];
    __shared__ float nqs[128];
    __shared__ float vsm[64];

    const int bh = blockIdx.x, sc = blockIdx.y;
    const int b = bh / NH, h = bh % NH;
    const int t = threadIdx.x;
    const int wid = t >> 5, lane = t & 31;
    const int grp = lane >> 2, tig = lane & 3;
    const uint32_t sQ = smem_u32(Qs);
    const uint32_t sT = smem_u32(kvT);

    auto load_q = [&](int st2, int buf) {
        int s0 = sc * 512 + st2 * 128;
        #pragma unroll
        for (int i = 0; i < 8; i++) {
            int s = t + i * 128;
            int row = s >> 3, ch = s & 7;
            CP_ASYNC16(sQ + buf * 16384 + SWZ((uint32_t)(row * 128 + ch * 16)),
                       g_Qh + ((size_t)(b * Ss + s0 + row)) * 768 + h * 64 + ch * 8);
        }
        CP_COMMIT();
    };

    load_q(0, 0);

    // build kvT once (transposed kv + ksum row + zero rows)
    for (int idx = t; idx < 80 * 64; idx += 128) {
        int n = idx >> 6, k = idx & 63;
        float v;
        if (n < 64)       v = g_red[KV_OFF + bh * 4096 + k * 64 + n];
        else if (n == 64) v = g_red[KSUM_OFF + bh * 64 + k];
        else              v = 0.0f;
        *(__half*)((char*)kvT + SWZ((uint32_t)(n * 128 + k * 2))) = __float2half_rn(v);
    }
    if (t < 64) vsm[t] = g_red[VSUM_OFF + bh * 64 + t];
    const float msum = g_red[MSUM_OFF + b];

    for (int st2 = 0; st2 < 4; st2++) {
        const int buf = st2 & 1;
        if (st2 + 1 < 4) {
            load_q(st2 + 1, buf ^ 1);
            asm volatile("cp.async.wait_group 1;" ::: "memory");
        } else {
            asm volatile("cp.async.wait_group 0;" ::: "memory");
        }
        __syncthreads();   // Q(st2) visible; prior iter's nqs reads complete

        const uint32_t Qb = sQ + buf * 16384;

        float acc[2][9][4];
        #pragma unroll
        for (int i = 0; i < 2; i++)
            #pragma unroll
            for (int j = 0; j < 9; j++)
                #pragma unroll
                for (int c = 0; c < 4; c++) acc[i][j][c] = 0.0f;

        #pragma unroll
        for (int ks = 0; ks < 4; ks++) {
            const int k0b = ks * 32;
            uint32_t afr[2][4];
            #pragma unroll
            for (int mt = 0; mt < 2; mt++) {
                int row = wid * 32 + mt * 16 + (lane & 15);
                LDMATRIX_X4(afr[mt], Qb + SWZ((uint32_t)(row * 128 + k0b + (lane >> 4) * 16)));
            }
            uint32_t bfr[5][4];
            #pragma unroll
            for (int bp = 0; bp < 5; bp++) {
                int row = bp * 16 + (lane & 7) + ((lane >> 4) << 3);
                LDMATRIX_X4(bfr[bp], sT + SWZ((uint32_t)(row * 128 + k0b + ((lane >> 3) & 1) * 16)));
            }
            #pragma unroll
            for (int mt = 0; mt < 2; mt++)
                #pragma unroll
                for (int nt = 0; nt < 9; nt++)
                    mma_f16(acc[mt][nt], afr[mt], &bfr[nt >> 1][(nt & 1) * 2]);
        }

        if (tig == 0) {
            #pragma unroll
            for (int mt = 0; mt < 2; mt++) {
                nqs[wid * 32 + mt * 16 + grp]     = acc[mt][8][0];
                nqs[wid * 32 + mt * 16 + grp + 8] = acc[mt][8][2];
            }
        }
        __syncthreads();

        const int srow = sc * 512 + st2 * 128;
        #pragma unroll
        for (int mt = 0; mt < 2; mt++) {
            int r0 = wid * 32 + mt * 16 + grp;
            float inv0 = 1.0f / (nqs[r0]     + EPS + msum);
            float inv1 = 1.0f / (nqs[r0 + 8] + EPS + msum);
            size_t g0 = ((size_t)(b * Ss + srow + r0))     * HID + h * HD;
            size_t g1 = ((size_t)(b * Ss + srow + r0 + 8)) * HID + h * HD;
            #pragma unroll
            for (int nt = 0; nt < 8; nt++) {
                int col = nt * 8 + tig * 2;
                float vx = vsm[col], vy = vsm[col + 1];
                float2 o0 = make_float2((acc[mt][nt][0] + vx) * inv0, (acc[mt][nt][1] + vy) * inv0);
                float2 o1 = make_float2((acc[mt][nt][2] + vx) * inv1, (acc[mt][nt][3] + vy) * inv1);
                *(float2*)&out[g0 + col] = o0;
                *(float2*)&out[g1 + col] = o1;
            }
        }
    }
}

// ---------------- launch ------------------------------------------------------
extern "C" void kernel_launch(void* const* d_in, const int* in_sizes, int n_in,
                              void* d_out, int out_size)
{
    const float* X  = (const float*)d_in[0];
    const float* am = (const float*)d_in[1];
    const float* Wq = (const float*)d_in[2];
    const float* bq = (const float*)d_in[3];
    const float* Wk = (const float*)d_in[4];
    const float* bk = (const float*)d_in[5];
    const float* Wv = (const float*)d_in[6];
    const float* bv = (const float*)d_in[7];
    float* out = (float*)d_out;

    cudaFuncSetAttribute(gemm_qkv_h, cudaFuncAttributeMaxDynamicSharedMemorySize, GK_SMEM);

    // gemm stays the 4th launch for ncu capture; msum only feeds out_mma.
    zero_kernel<<<(RED_TOTAL + 255) / 256, 256>>>();                       // 1
    convX_kernel<<<(ROWS * HID / 4) / 256, 256>>>(X);                      // 2
    convW_kernel<<<(3 * HID * HID / 4) / 256, 256>>>(Wq, Wk, Wv);          // 3

    dim3 g1(18, 256);
    gemm_qkv_h<<<g1, 128, GK_SMEM>>>(am, bq, bk, bv);                      // 4

    msum_kernel<<<Bb, 256>>>(am);                                          // 5

    dim3 g3(48, 16);
    kv_mma<<<g3, 160>>>();                                                 // 6

    dim3 g4(48, 16);
    out_mma<<<g4, 128>>>(out);                                             // 7
}

// round 12
// speedup vs baseline: 1.4687x; 1.0134x over previous
#include <cuda_runtime.h>
#include <cuda_fp16.h>
#include <cstdint>

// Problem constants
#define Bb   4
#define Ss   8192
#define HID  768
#define NH   12
#define HD   64
#define ROWS (Bb*Ss)          // 32768
#define EPS  1e-5f

// ---------------- scratch (device globals; no allocations allowed) ----------
__device__ __half g_Qh[(size_t)ROWS * HID];
__device__ __half g_Kh[(size_t)ROWS * HID];
__device__ __half g_Vh[(size_t)ROWS * HID];
__device__ __half g_Xh[(size_t)ROWS * HID];          // fp16 copy of X
__device__ __half g_Wh[(size_t)3 * HID * HID];       // fp16 [Wq;Wk;Wv]

#define KV_OFF   0                       // 48 * 64 * 64 = 196608
#define KSUM_OFF (48*4096)
#define VSUM_OFF (KSUM_OFF + 48*64)
#define MSUM_OFF (VSUM_OFF + 48*64)
#define RED_TOTAL (MSUM_OFF + 4)         // 202756 floats
#define RED_N4    ((RED_TOTAL + 3) / 4)  // 50689 float4s
__device__ float g_red[RED_N4 * 4];

// ================= helpers ====================================================
__device__ __forceinline__ uint32_t smem_u32(const void* p) {
    uint32_t a;
    asm("{ .reg .u64 t; cvta.to.shared.u64 t, %1; cvt.u32.u64 %0, t; }" : "=r"(a) : "l"(p));
    return a;
}
#define CP_ASYNC16(dst, src) \
    asm volatile("cp.async.cg.shared.global [%0], [%1], 16;" :: "r"((uint32_t)(dst)), "l"(src) : "memory")
#define CP_COMMIT() asm volatile("cp.async.commit_group;" ::: "memory")
#define SWZ(o) ((o) ^ (((o) >> 3) & 0x70))

__device__ __forceinline__ void mma_f16(float* d, const uint32_t* a, const uint32_t* b) {
    asm volatile(
        "mma.sync.aligned.m16n8k16.row.col.f32.f16.f16.f32 "
        "{%0,%1,%2,%3}, {%4,%5,%6,%7}, {%8,%9}, {%0,%1,%2,%3};"
        : "+f"(d[0]), "+f"(d[1]), "+f"(d[2]), "+f"(d[3])
        : "r"(a[0]), "r"(a[1]), "r"(a[2]), "r"(a[3]), "r"(b[0]), "r"(b[1]));
}
#define LDMATRIX_X4(r, addr) \
    asm volatile("ldmatrix.sync.aligned.m8n8.x4.shared.b16 {%0,%1,%2,%3}, [%4];" \
        : "=r"((r)[0]), "=r"((r)[1]), "=r"((r)[2]), "=r"((r)[3]) : "r"(addr))
#define LDMATRIX_X4_T(r, addr) \
    asm volatile("ldmatrix.sync.aligned.m8n8.x4.trans.shared.b16 {%0,%1,%2,%3}, [%4];" \
        : "=r"((r)[0]), "=r"((r)[1]), "=r"((r)[2]), "=r"((r)[3]) : "r"(addr))
#define ONES2 0x3C003C00u   // half2(1.0, 1.0)

// ---------------- K-1a: fp32 -> fp16 converter for X ---------------------------
__global__ void convX_kernel(const float* __restrict__ X) {
    size_t i = (size_t)blockIdx.x * 256 + threadIdx.x;
    float4 v = ((const float4*)X)[i];
    ((__half2*)g_Xh)[2*i]   = __floats2half2_rn(v.x, v.y);
    ((__half2*)g_Xh)[2*i+1] = __floats2half2_rn(v.z, v.w);
}

// ---------------- K-1b: converter for W + zero of g_red (fused) ---------------
#define WBLKS 1728                      // 3*768*768/4 float4s / 256 threads
#define ZBLKS ((RED_N4 + 255) / 256)    // 199
__global__ void convW_kernel(const float* __restrict__ Wq,
                             const float* __restrict__ Wk,
                             const float* __restrict__ Wv) {
    if (blockIdx.x >= WBLKS) {
        size_t z = (size_t)(blockIdx.x - WBLKS) * 256 + threadIdx.x;
        if (z < RED_N4) ((float4*)g_red)[z] = make_float4(0.f, 0.f, 0.f, 0.f);
        return;
    }
    size_t i = (size_t)blockIdx.x * 256 + threadIdx.x;
    const size_t per = (size_t)HID * HID / 4;
    const float* src = (i < per) ? Wq : (i < 2*per) ? Wk : Wv;
    size_t j = i % per;
    float4 v = ((const float4*)src)[j];
    ((__half2*)g_Wh)[2*i]   = __floats2half2_rn(v.x, v.y);
    ((__half2*)g_Wh)[2*i+1] = __floats2half2_rn(v.z, v.w);
}

// ---------------- K1: fused QKV projection (fp16 HMMA) + mask + L2-norm -------
// C = X[32768,768] @ W^T. CTA tile 128x128x64, 4 warps (2m x 2n), warp 64x64.
// 3 smem stages; per-iter: wait(load kt) -> sync -> prefetch(kt+2) -> compute.
// Inner loop: B fragments per ks, A fragments one mt at a time (low reg live).
#define GK_SMEM (6 * 16384)    // A 3x16KB + B 3x16KB

__global__ void __launch_bounds__(128, 2) gemm_qkv_h(
    const float* __restrict__ am,
    const float* __restrict__ bq, const float* __restrict__ bk, const float* __restrict__ bv)
{
    extern __shared__ char smem[];
    const uint32_t sb = smem_u32(smem);

    const int t    = threadIdx.x;
    const int wid  = t >> 5, lane = t & 31;
    const int wm   = wid & 1;           // 2 warps in m
    const int wn   = wid >> 1;          // 2 warps in n
    const int grp  = lane >> 2, tig = lane & 3;

    const int nb = blockIdx.x;          // 0..17
    const int mb = blockIdx.y;          // 0..255
    const int mat = nb / 6;             // 0=q 1=k 2=v
    const float* bias = (mat == 0) ? bq : (mat == 1) ? bk : bv;
    __half* C         = (mat == 0) ? g_Qh : (mat == 1) ? g_Kh : g_Vh;
    const int n0 = (nb % 6) * 128;
    const int m0 = mb * 128;

    const __half* Asrc = g_Xh + (size_t)m0 * 768;
    const __half* Bsrc = g_Wh + (size_t)nb * 128 * 768;

    auto load_tile = [&](int kt, int stg) {
        uint32_t Ad = sb + stg * 16384;
        uint32_t Bd = sb + 49152 + stg * 16384;
        #pragma unroll
        for (int i = 0; i < 8; i++) {
            int s   = t + i * 128;          // 0..1023
            int row = s >> 3, ch = s & 7;
            uint32_t off = SWZ((uint32_t)(row * 128 + ch * 16));
            CP_ASYNC16(Ad + off, Asrc + (size_t)row * 768 + kt * 64 + ch * 8);
            CP_ASYNC16(Bd + off, Bsrc + (size_t)row * 768 + kt * 64 + ch * 8);
        }
        CP_COMMIT();
    };

    float acc[4][8][4];
    #pragma unroll
    for (int i = 0; i < 4; i++)
        #pragma unroll
        for (int j = 0; j < 8; j++)
            #pragma unroll
            for (int c = 0; c < 4; c++) acc[i][j][c] = 0.0f;

    load_tile(0, 0);
    load_tile(1, 1);

    for (int kt = 0; kt < 12; kt++) {
        const int buf = kt % 3;
        if (kt < 11) asm volatile("cp.async.wait_group 1;" ::: "memory");
        else         asm volatile("cp.async.wait_group 0;" ::: "memory");
        __syncthreads();   // everyone's load(kt) visible + compute(kt-1) done
        if (kt + 2 < 12) load_tile(kt + 2, (kt + 2) % 3);

        const uint32_t Abase = sb + buf * 16384;
        const uint32_t Bbase = sb + 49152 + buf * 16384;

        #pragma unroll
        for (int ks = 0; ks < 4; ks++) {
            const int k0b = ks * 32;
            uint32_t bfr[4][4];
            #pragma unroll
            for (int bp = 0; bp < 4; bp++) {
                int row = wn * 64 + bp * 16 + (lane & 7) + ((lane >> 4) << 3);
                LDMATRIX_X4(bfr[bp], Bbase + SWZ((uint32_t)(row * 128 + k0b + ((lane >> 3) & 1) * 16)));
            }
            #pragma unroll
            for (int mt = 0; mt < 4; mt++) {
                uint32_t afr[4];
                int row = wm * 64 + mt * 16 + (lane & 15);
                LDMATRIX_X4(afr, Abase + SWZ((uint32_t)(row * 128 + k0b + (lane >> 4) * 16)));
                #pragma unroll
                for (int nt = 0; nt < 8; nt++)
                    mma_f16(acc[mt][nt], afr, &bfr[nt >> 1][(nt & 1) * 2]);
            }
        }
    }

    // -------- epilogue (warp-local: this warp's 64 cols = one head) --------
    const int colbase = n0 + wn * 64;
    float bx[8], by[8];
    #pragma unroll
    for (int nt = 0; nt < 8; nt++) {
        bx[nt] = bias[colbase + nt * 8 + tig * 2];
        by[nt] = bias[colbase + nt * 8 + tig * 2 + 1];
    }

    if (mat < 2) {
        #pragma unroll
        for (int mt = 0; mt < 4; mt++) {
            const int r0 = m0 + wm * 64 + mt * 16 + grp;
            const float mr0 = (am[r0]     != 0.0f) ? 0.0f : 1.0f;
            const float mr1 = (am[r0 + 8] != 0.0f) ? 0.0f : 1.0f;
            float ssq0 = 0.0f, ssq1 = 0.0f;
            #pragma unroll
            for (int nt = 0; nt < 8; nt++) {
                float a0 = (acc[mt][nt][0] + bx[nt]) * mr0;
                float a1 = (acc[mt][nt][1] + by[nt]) * mr0;
                float a2 = (acc[mt][nt][2] + bx[nt]) * mr1;
                float a3 = (acc[mt][nt][3] + by[nt]) * mr1;
                acc[mt][nt][0] = a0; acc[mt][nt][1] = a1;
                acc[mt][nt][2] = a2; acc[mt][nt][3] = a3;
                ssq0 += a0*a0 + a1*a1;
                ssq1 += a2*a2 + a3*a3;
            }
            #pragma unroll
            for (int off = 1; off <= 2; off <<= 1) {
                ssq0 += __shfl_xor_sync(0xffffffffu, ssq0, off);
                ssq1 += __shfl_xor_sync(0xffffffffu, ssq1, off);
            }
            const float inv0 = 1.0f / (sqrtf(ssq0) + EPS);
            const float inv1 = 1.0f / (sqrtf(ssq1) + EPS);
            #pragma unroll
            for (int nt = 0; nt < 8; nt++) {
                size_t gc = (size_t)r0 * 768 + colbase + nt * 8 + tig * 2;
                *(__half2*)&C[gc]           = __floats2half2_rn(acc[mt][nt][0] * inv0, acc[mt][nt][1] * inv0);
                *(__half2*)&C[gc + 8 * 768] = __floats2half2_rn(acc[mt][nt][2] * inv1, acc[mt][nt][3] * inv1);
            }
        }
    } else {
        #pragma unroll
        for (int mt = 0; mt < 4; mt++) {
            const int r0 = m0 + wm * 64 + mt * 16 + grp;
            #pragma unroll
            for (int nt = 0; nt < 8; nt++) {
                size_t gc = (size_t)r0 * 768 + colbase + nt * 8 + tig * 2;
                *(__half2*)&C[gc]           = __floats2half2_rn(acc[mt][nt][0] + bx[nt], acc[mt][nt][1] + by[nt]);
                *(__half2*)&C[gc + 8 * 768] = __floats2half2_rn(acc[mt][nt][2] + bx[nt], acc[mt][nt][3] + by[nt]);
            }
        }
    }
}

// ---------------- K2b: msum per batch ----------------------------------------
__global__ void msum_kernel(const float* __restrict__ am) {
    __shared__ float red[256];
    int b = blockIdx.x;
    float s = 0.0f;
    for (int i = threadIdx.x; i < Ss; i += 256)
        s += (am[b * Ss + i] != 0.0f) ? 0.0f : 1.0f;
    red[threadIdx.x] = s;
    __syncthreads();
    for (int o = 128; o; o >>= 1) {
        if (threadIdx.x < o) red[threadIdx.x] += red[threadIdx.x + o];
        __syncthreads();
    }
    if (threadIdx.x == 0) g_red[MSUM_OFF + b] = red[0];
}

// ---------------- K3: kv = K^T V (+ ksum, vsum) via HMMA ----------------------
__global__ void __launch_bounds__(160) kv_mma() {
    __shared__ __half Ks[2][64 * 64];
    __shared__ __half Vs[2][64 * 64];

    const int bh = blockIdx.x, sc = blockIdx.y;
    const int b = bh / NH, h = bh % NH;
    const int t = threadIdx.x;
    const int wid = t >> 5, lane = t & 31;
    const int grp = lane >> 2, tig = lane & 3;
    const uint32_t sK = smem_u32(Ks);
    const uint32_t sV = smem_u32(Vs);
    const int s_base = sc * 512;

    auto load_tile = [&](int tile, int buf) {
        int s0 = s_base + tile * 64;
        for (int i = t; i < 1024; i += 160) {
            int isV = i >> 9;
            int j = i & 511;
            int row = j >> 3, ch = j & 7;
            uint32_t off = SWZ((uint32_t)(row * 128 + ch * 16));
            const __half* src = (isV ? g_Vh : g_Kh)
                + ((size_t)(b * Ss + s0 + row)) * 768 + h * 64 + ch * 8;
            CP_ASYNC16((isV ? sV : sK) + buf * 8192 + off, src);
        }
        CP_COMMIT();
    };

    float acc[9][4];
    #pragma unroll
    for (int j = 0; j < 9; j++)
        #pragma unroll
        for (int c = 0; c < 4; c++) acc[j][c] = 0.0f;

    uint32_t a_ones[4];
    a_ones[0] = (grp == 0) ? ONES2 : 0u;
    a_ones[1] = 0u;
    a_ones[2] = (grp == 0) ? ONES2 : 0u;
    a_ones[3] = 0u;
    uint32_t b_ones[2];
    b_ones[0] = (grp == 0) ? ONES2 : 0u;
    b_ones[1] = (grp == 0) ? ONES2 : 0u;

    load_tile(0, 0);

    for (int tile = 0; tile < 8; tile++) {
        const int buf = tile & 1;
        if (tile + 1 < 8) {
            load_tile(tile + 1, buf ^ 1);
            asm volatile("cp.async.wait_group 1;" ::: "memory");
        } else {
            asm volatile("cp.async.wait_group 0;" ::: "memory");
        }
        __syncthreads();

        const uint32_t Kb = sK + buf * 8192;
        const uint32_t Vb = sV + buf * 8192;

        #pragma unroll
        for (int ks = 0; ks < 4; ks++) {
            uint32_t afr[4];
            if (wid < 4) {
                int row = ks * 16 + ((lane >> 4) << 3) + (lane & 7);
                LDMATRIX_X4_T(afr, Kb + SWZ((uint32_t)(row * 128 + wid * 32 + ((lane >> 3) & 1) * 16)));
            } else {
                afr[0] = a_ones[0]; afr[1] = a_ones[1];
                afr[2] = a_ones[2]; afr[3] = a_ones[3];
            }
            uint32_t bfr[4][4];
            #pragma unroll
            for (int bp = 0; bp < 4; bp++) {
                int row = ks * 16 + (((lane >> 3) & 1) << 3) + (lane & 7);
                LDMATRIX_X4_T(bfr[bp], Vb + SWZ((uint32_t)(row * 128 + bp * 32 + (lane >> 4) * 16)));
            }
            #pragma unroll
            for (int nt = 0; nt < 8; nt++)
                mma_f16(acc[nt], afr, &bfr[nt >> 1][(nt & 1) * 2]);
            mma_f16(acc[8], afr, b_ones);
        }
        __syncthreads();
    }

    float* kvb = g_red + KV_OFF + bh * 4096;
    if (wid < 4) {
        int d = wid * 16 + grp;
        #pragma unroll
        for (int nt = 0; nt < 8; nt++) {
            int e = nt * 8 + tig * 2;
            atomicAdd(&kvb[d * 64 + e],           acc[nt][0]);
            atomicAdd(&kvb[d * 64 + e + 1],       acc[nt][1]);
            atomicAdd(&kvb[(d + 8) * 64 + e],     acc[nt][2]);
            atomicAdd(&kvb[(d + 8) * 64 + e + 1], acc[nt][3]);
        }
        if (tig == 0) {
            atomicAdd(&g_red[KSUM_OFF + bh * 64 + d],     acc[8][0]);
            atomicAdd(&g_red[KSUM_OFF + bh * 64 + d + 8], acc[8][2]);
        }
    } else if (grp == 0) {
        #pragma unroll
        for (int nt = 0; nt < 8; nt++) {
            int e = nt * 8 + tig * 2;
            atomicAdd(&g_red[VSUM_OFF + bh * 64 + e],     acc[nt][0]);
            atomicAdd(&g_red[VSUM_OFF + bh * 64 + e + 1], acc[nt][1]);
        }
    }
}

// ---------------- K4: out via fp16 HMMA, 4 q-tiles per CTA --------------------
// Grid (48, 16): CTA covers 512 s-rows of one (b,h); kvT/vsum built once.
__global__ void __launch_bounds__(128) out_mma(float* __restrict__ out) {
    __shared__ __half Qs[2][128 * 64];
    __shared__ __half kvT[80 * 64];
    __shared__ float nqs[128];
    __shared__ float vsm[64];

    const int bh = blockIdx.x, sc = blockIdx.y;
    const int b = bh / NH, h = bh % NH;
    const int t = threadIdx.x;
    const int wid = t >> 5, lane = t & 31;
    const int grp = lane >> 2, tig = lane & 3;
    const uint32_t sQ = smem_u32(Qs);
    const uint32_t sT = smem_u32(kvT);

    auto load_q = [&](int st2, int buf) {
        int s0 = sc * 512 + st2 * 128;
        #pragma unroll
        for (int i = 0; i < 8; i++) {
            int s = t + i * 128;
            int row = s >> 3, ch = s & 7;
            CP_ASYNC16(sQ + buf * 16384 + SWZ((uint32_t)(row * 128 + ch * 16)),
                       g_Qh + ((size_t)(b * Ss + s0 + row)) * 768 + h * 64 + ch * 8);
        }
        CP_COMMIT();
    };

    load_q(0, 0);

    // build kvT once (transposed kv + ksum row + zero rows)
    for (int idx = t; idx < 80 * 64; idx += 128) {
        int n = idx >> 6, k = idx & 63;
        float v;
        if (n < 64)       v = g_red[KV_OFF + bh * 4096 + k * 64 + n];
        else if (n == 64) v = g_red[KSUM_OFF + bh * 64 + k];
        else              v = 0.0f;
        *(__half*)((char*)kvT + SWZ((uint32_t)(n * 128 + k * 2))) = __float2half_rn(v);
    }
    if (t < 64) vsm[t] = g_red[VSUM_OFF + bh * 64 + t];
    const float msum = g_red[MSUM_OFF + b];

    for (int st2 = 0; st2 < 4; st2++) {
        const int buf = st2 & 1;
        if (st2 + 1 < 4) {
            load_q(st2 + 1, buf ^ 1);
            asm volatile("cp.async.wait_group 1;" ::: "memory");
        } else {
            asm volatile("cp.async.wait_group 0;" ::: "memory");
        }
        __syncthreads();   // Q(st2) visible; prior iter's nqs reads complete

        const uint32_t Qb = sQ + buf * 16384;

        float acc[2][9][4];
        #pragma unroll
        for (int i = 0; i < 2; i++)
            #pragma unroll
            for (int j = 0; j < 9; j++)
                #pragma unroll
                for (int c = 0; c < 4; c++) acc[i][j][c] = 0.0f;

        #pragma unroll
        for (int ks = 0; ks < 4; ks++) {
            const int k0b = ks * 32;
            uint32_t afr[2][4];
            #pragma unroll
            for (int mt = 0; mt < 2; mt++) {
                int row = wid * 32 + mt * 16 + (lane & 15);
                LDMATRIX_X4(afr[mt], Qb + SWZ((uint32_t)(row * 128 + k0b + (lane >> 4) * 16)));
            }
            uint32_t bfr[5][4];
            #pragma unroll
            for (int bp = 0; bp < 5; bp++) {
                int row = bp * 16 + (lane & 7) + ((lane >> 4) << 3);
                LDMATRIX_X4(bfr[bp], sT + SWZ((uint32_t)(row * 128 + k0b + ((lane >> 3) & 1) * 16)));
            }
            #pragma unroll
            for (int mt = 0; mt < 2; mt++)
                #pragma unroll
                for (int nt = 0; nt < 9; nt++)
                    mma_f16(acc[mt][nt], afr[mt], &bfr[nt >> 1][(nt & 1) * 2]);
        }

        if (tig == 0) {
            #pragma unroll
            for (int mt = 0; mt < 2; mt++) {
                nqs[wid * 32 + mt * 16 + grp]     = acc[mt][8][0];
                nqs[wid * 32 + mt * 16 + grp + 8] = acc[mt][8][2];
            }
        }
        __syncthreads();

        const int srow = sc * 512 + st2 * 128;
        #pragma unroll
        for (int mt = 0; mt < 2; mt++) {
            int r0 = wid * 32 + mt * 16 + grp;
            float inv0 = 1.0f / (nqs[r0]     + EPS + msum);
            float inv1 = 1.0f / (nqs[r0 + 8] + EPS + msum);
            size_t g0 = ((size_t)(b * Ss + srow + r0))     * HID + h * HD;
            size_t g1 = ((size_t)(b * Ss + srow + r0 + 8)) * HID + h * HD;
            #pragma unroll
            for (int nt = 0; nt < 8; nt++) {
                int col = nt * 8 + tig * 2;
                float vx = vsm[col], vy = vsm[col + 1];
                float2 o0 = make_float2((acc[mt][nt][0] + vx) * inv0, (acc[mt][nt][1] + vy) * inv0);
                float2 o1 = make_float2((acc[mt][nt][2] + vx) * inv1, (acc[mt][nt][3] + vy) * inv1);
                *(float2*)&out[g0 + col] = o0;
                *(float2*)&out[g1 + col] = o1;
            }
        }
    }
}

// ---------------- launch ------------------------------------------------------
extern "C" void kernel_launch(void* const* d_in, const int* in_sizes, int n_in,
                              void* d_out, int out_size)
{
    const float* X  = (const float*)d_in[0];
    const float* am = (const float*)d_in[1];
    const float* Wq = (const float*)d_in[2];
    const float* bq = (const float*)d_in[3];
    const float* Wk = (const float*)d_in[4];
    const float* bk = (const float*)d_in[5];
    const float* Wv = (const float*)d_in[6];
    const float* bv = (const float*)d_in[7];
    float* out = (float*)d_out;

    cudaFuncSetAttribute(gemm_qkv_h, cudaFuncAttributeMaxDynamicSharedMemorySize, GK_SMEM);

    // gemm stays the 4th launch for ncu capture; msum only feeds out_mma.
    convX_kernel<<<(ROWS * HID / 4) / 256, 256>>>(X);                      // 1
    convW_kernel<<<WBLKS + ZBLKS, 256>>>(Wq, Wk, Wv);                      // 2 (conv + zero)
    msum_kernel<<<Bb, 256>>>(am);                                          // 3

    dim3 g1(18, 256);
    gemm_qkv_h<<<g1, 128, GK_SMEM>>>(am, bq, bk, bv);                      // 4

    dim3 g3(48, 16);
    kv_mma<<<g3, 160>>>();                                                 // 5

    dim3 g4(48, 16);
    out_mma<<<g4, 128>>>(out);                                             // 6
}

// round 13
// speedup vs baseline: 1.5839x; 1.0785x over previous
#include <cuda_runtime.h>
#include <cuda_fp16.h>
#include <cuda.h>
#include <cstdint>

// Problem constants
#define Bb   4
#define Ss   8192
#define HID  768
#define NH   12
#define HD   64
#define ROWS (Bb*Ss)          // 32768
#define EPS  1e-5f

// ---------------- scratch (device globals; no allocations allowed) ----------
__device__ __half g_Qh[(size_t)ROWS * HID];
__device__ __half g_Kh[(size_t)ROWS * HID];
__device__ __half g_Vh[(size_t)ROWS * HID];
__device__ __half g_Xh[(size_t)ROWS * HID];          // fp16 copy of X
__device__ __half g_Wh[(size_t)3 * HID * HID];       // fp16 [Wq;Wk;Wv]

#define KV_OFF   0                       // 48 * 64 * 64 = 196608
#define KSUM_OFF (48*4096)
#define VSUM_OFF (KSUM_OFF + 48*64)
#define MSUM_OFF (VSUM_OFF + 48*64)
#define RED_TOTAL (MSUM_OFF + 4)         // 202756 floats
#define RED_N4    ((RED_TOTAL + 3) / 4)
__device__ float g_red[RED_N4 * 4];

// ================= helpers ====================================================
__device__ __forceinline__ uint32_t smem_u32(const void* p) {
    uint32_t a;
    asm("{ .reg .u64 t; cvta.to.shared.u64 t, %1; cvt.u32.u64 %0, t; }" : "=r"(a) : "l"(p));
    return a;
}
#define CP_ASYNC16(dst, src) \
    asm volatile("cp.async.cg.shared.global [%0], [%1], 16;" :: "r"((uint32_t)(dst)), "l"(src) : "memory")
#define CP_COMMIT() asm volatile("cp.async.commit_group;" ::: "memory")
#define SWZ(o) ((o) ^ (((o) >> 3) & 0x70))

__device__ __forceinline__ void mma_f16(float* d, const uint32_t* a, const uint32_t* b) {
    asm volatile(
        "mma.sync.aligned.m16n8k16.row.col.f32.f16.f16.f32 "
        "{%0,%1,%2,%3}, {%4,%5,%6,%7}, {%8,%9}, {%0,%1,%2,%3};"
        : "+f"(d[0]), "+f"(d[1]), "+f"(d[2]), "+f"(d[3])
        : "r"(a[0]), "r"(a[1]), "r"(a[2]), "r"(a[3]), "r"(b[0]), "r"(b[1]));
}
#define LDMATRIX_X4(r, addr) \
    asm volatile("ldmatrix.sync.aligned.m8n8.x4.shared.b16 {%0,%1,%2,%3}, [%4];" \
        : "=r"((r)[0]), "=r"((r)[1]), "=r"((r)[2]), "=r"((r)[3]) : "r"(addr))
#define LDMATRIX_X4_T(r, addr) \
    asm volatile("ldmatrix.sync.aligned.m8n8.x4.trans.shared.b16 {%0,%1,%2,%3}, [%4];" \
        : "=r"((r)[0]), "=r"((r)[1]), "=r"((r)[2]), "=r"((r)[3]) : "r"(addr))
#define ONES2 0x3C003C00u   // half2(1.0, 1.0)

#define MBARRIER_INIT(mbar, cnt) \
    asm volatile("mbarrier.init.shared.b64 [%0], %1;" :: "r"((uint32_t)(mbar)), "r"((uint32_t)(cnt)) : "memory")
#define MBARRIER_EXPECT_TX(mbar, bytes) \
    asm volatile("mbarrier.arrive.expect_tx.shared.b64 _, [%0], %1;" :: "r"((uint32_t)(mbar)), "r"((uint32_t)(bytes)) : "memory")
#define MBARRIER_WAIT_PARITY(mbar, parity) do { \
    uint32_t _m = (uint32_t)(mbar); uint32_t _p = (uint32_t)(parity); uint32_t _d; \
    asm volatile("{\n\t.reg .pred p;\n\t" \
        "mbarrier.try_wait.parity.acquire.cta.shared::cta.b64 p, [%1], %2;\n\t" \
        "selp.b32 %0, 1, 0, p;\n\t}" : "=r"(_d) : "r"(_m), "r"(_p) : "memory"); \
    if (!_d) { \
        asm volatile("{\n\t.reg .pred P1;\n\t" \
            "WL_%=:\n\t" \
            "mbarrier.try_wait.parity.acquire.cta.shared::cta.b64 P1, [%0], %1, 0x989680;\n\t" \
            "@P1 bra.uni WD_%=;\n\t" \
            "bra.uni WL_%=;\n\t" \
            "WD_%=:\n\t}" :: "r"(_m), "r"(_p) : "memory"); \
    } } while(0)
#define TMA_LOAD_2D(smem_addr, tmap_ptr, cx, cy, mbar) \
    asm volatile("cp.async.bulk.tensor.2d.shared::cta.global.tile.mbarrier::complete_tx::bytes " \
        "[%0], [%1, {%2, %3}], [%4];" \
        :: "r"((uint32_t)(smem_addr)), "l"(tmap_ptr), "r"((int)(cx)), "r"((int)(cy)), \
           "r"((uint32_t)(mbar)) : "memory")

// ---------------- K-1a: fp32 -> fp16 converter for X ---------------------------
__global__ void convX_kernel(const float* __restrict__ X) {
    size_t i = (size_t)blockIdx.x * 256 + threadIdx.x;
    float4 v = ((const float4*)X)[i];
    ((__half2*)g_Xh)[2*i]   = __floats2half2_rn(v.x, v.y);
    ((__half2*)g_Xh)[2*i+1] = __floats2half2_rn(v.z, v.w);
}

// ---------------- K-1b: converter for W + zero of g_red (fused) ---------------
#define WBLKS 1728
#define ZBLKS ((RED_N4 + 255) / 256)
__global__ void convW_kernel(const float* __restrict__ Wq,
                             const float* __restrict__ Wk,
                             const float* __restrict__ Wv) {
    if (blockIdx.x >= WBLKS) {
        size_t z = (size_t)(blockIdx.x - WBLKS) * 256 + threadIdx.x;
        if (z < RED_N4) ((float4*)g_red)[z] = make_float4(0.f, 0.f, 0.f, 0.f);
        return;
    }
    size_t i = (size_t)blockIdx.x * 256 + threadIdx.x;
    const size_t per = (size_t)HID * HID / 4;
    const float* src = (i < per) ? Wq : (i < 2*per) ? Wk : Wv;
    size_t j = i % per;
    float4 v = ((const float4*)src)[j];
    ((__half2*)g_Wh)[2*i]   = __floats2half2_rn(v.x, v.y);
    ((__half2*)g_Wh)[2*i+1] = __floats2half2_rn(v.z, v.w);
}

// ---------------- K1: fused QKV projection (fp16 HMMA, TMA loads) -------------
// C = X[32768,768] @ W^T. CTA tile 128x128x64, 4 warps (2m x 2n), warp 64x64.
// 3 smem stages fed by TMA (one thread issues 2 bulk loads per stage);
// per-stage mbarrier with expect_tx; compute path identical to cp.async version.
#define GK_SMEM (6 * 16384 + 64)   // A 3x16KB + B 3x16KB + mbarriers

__global__ void __launch_bounds__(128, 2) gemm_qkv_h(
    const __grid_constant__ CUtensorMap tmX,
    const __grid_constant__ CUtensorMap tmW,
    const float* __restrict__ am,
    const float* __restrict__ bq, const float* __restrict__ bk, const float* __restrict__ bv)
{
    extern __shared__ char smem[];
    const uint32_t sb = smem_u32(smem);
    const uint32_t mb = sb + 98304;      // 3 mbarriers, 8B each

    const int t    = threadIdx.x;
    const int wid  = t >> 5, lane = t & 31;
    const int wm   = wid & 1;           // 2 warps in m
    const int wn   = wid >> 1;          // 2 warps in n
    const int grp  = lane >> 2, tig = lane & 3;

    const int nb = blockIdx.x;          // 0..17
    const int mbk = blockIdx.y;         // 0..255
    const int mat = nb / 6;             // 0=q 1=k 2=v
    const float* bias = (mat == 0) ? bq : (mat == 1) ? bk : bv;
    __half* C         = (mat == 0) ? g_Qh : (mat == 1) ? g_Kh : g_Vh;
    const int n0 = (nb % 6) * 128;
    const int m0 = mbk * 128;
    const int wrow0 = nb * 128;         // row base within g_Wh [2304, 768]

    if (t == 0) {
        MBARRIER_INIT(mb + 0, 1);
        MBARRIER_INIT(mb + 8, 1);
        MBARRIER_INIT(mb + 16, 1);
        asm volatile("fence.proxy.async.shared::cta;" ::: "memory");
    }
    __syncthreads();

    auto issue = [&](int kt, int stg) {   // t==0 only
        uint32_t bar = mb + stg * 8;
        MBARRIER_EXPECT_TX(bar, 32768u);
        TMA_LOAD_2D(sb + stg * 16384,         &tmX, kt * 64, m0,    bar);
        TMA_LOAD_2D(sb + 49152 + stg * 16384, &tmW, kt * 64, wrow0, bar);
    };

    float acc[4][8][4];
    #pragma unroll
    for (int i = 0; i < 4; i++)
        #pragma unroll
        for (int j = 0; j < 8; j++)
            #pragma unroll
            for (int c = 0; c < 4; c++) acc[i][j][c] = 0.0f;

    if (t == 0) { issue(0, 0); issue(1, 1); }

    for (int kt = 0; kt < 12; kt++) {
        const int buf = kt % 3;
        MBARRIER_WAIT_PARITY(mb + buf * 8, (kt / 3) & 1);  // data(kt) ready
        __syncthreads();   // all warps passed wait(kt) => compute(kt-1) done
        // stage (kt+2)%3 == (kt-1)%3, freed by the barrier above
        if (t == 0 && kt + 2 < 12) issue(kt + 2, (kt + 2) % 3);

        const uint32_t Abase = sb + buf * 16384;
        const uint32_t Bbase = sb + 49152 + buf * 16384;

        #pragma unroll
        for (int ks = 0; ks < 4; ks++) {
            const int k0b = ks * 32;
            uint32_t bfr[4][4];
            #pragma unroll
            for (int bp = 0; bp < 4; bp++) {
                int row = wn * 64 + bp * 16 + (lane & 7) + ((lane >> 4) << 3);
                LDMATRIX_X4(bfr[bp], Bbase + SWZ((uint32_t)(row * 128 + k0b + ((lane >> 3) & 1) * 16)));
            }
            #pragma unroll
            for (int mt = 0; mt < 4; mt++) {
                uint32_t afr[4];
                int row = wm * 64 + mt * 16 + (lane & 15);
                LDMATRIX_X4(afr, Abase + SWZ((uint32_t)(row * 128 + k0b + (lane >> 4) * 16)));
                #pragma unroll
                for (int nt = 0; nt < 8; nt++)
                    mma_f16(acc[mt][nt], afr, &bfr[nt >> 1][(nt & 1) * 2]);
            }
        }
    }

    // -------- epilogue (warp-local: this warp's 64 cols = one head) --------
    const int colbase = n0 + wn * 64;
    float bx[8], by[8];
    #pragma unroll
    for (int nt = 0; nt < 8; nt++) {
        bx[nt] = bias[colbase + nt * 8 + tig * 2];
        by[nt] = bias[colbase + nt * 8 + tig * 2 + 1];
    }

    if (mat < 2) {
        #pragma unroll
        for (int mt = 0; mt < 4; mt++) {
            const int r0 = m0 + wm * 64 + mt * 16 + grp;
            const float mr0 = (am[r0]     != 0.0f) ? 0.0f : 1.0f;
            const float mr1 = (am[r0 + 8] != 0.0f) ? 0.0f : 1.0f;
            float ssq0 = 0.0f, ssq1 = 0.0f;
            #pragma unroll
            for (int nt = 0; nt < 8; nt++) {
                float a0 = (acc[mt][nt][0] + bx[nt]) * mr0;
                float a1 = (acc[mt][nt][1] + by[nt]) * mr0;
                float a2 = (acc[mt][nt][2] + bx[nt]) * mr1;
                float a3 = (acc[mt][nt][3] + by[nt]) * mr1;
                acc[mt][nt][0] = a0; acc[mt][nt][1] = a1;
                acc[mt][nt][2] = a2; acc[mt][nt][3] = a3;
                ssq0 += a0*a0 + a1*a1;
                ssq1 += a2*a2 + a3*a3;
            }
            #pragma unroll
            for (int off = 1; off <= 2; off <<= 1) {
                ssq0 += __shfl_xor_sync(0xffffffffu, ssq0, off);
                ssq1 += __shfl_xor_sync(0xffffffffu, ssq1, off);
            }
            const float inv0 = 1.0f / (sqrtf(ssq0) + EPS);
            const float inv1 = 1.0f / (sqrtf(ssq1) + EPS);
            #pragma unroll
            for (int nt = 0; nt < 8; nt++) {
                size_t gc = (size_t)r0 * 768 + colbase + nt * 8 + tig * 2;
                *(__half2*)&C[gc]           = __floats2half2_rn(acc[mt][nt][0] * inv0, acc[mt][nt][1] * inv0);
                *(__half2*)&C[gc + 8 * 768] = __floats2half2_rn(acc[mt][nt][2] * inv1, acc[mt][nt][3] * inv1);
            }
        }
    } else {
        #pragma unroll
        for (int mt = 0; mt < 4; mt++) {
            const int r0 = m0 + wm * 64 + mt * 16 + grp;
            #pragma unroll
            for (int nt = 0; nt < 8; nt++) {
                size_t gc = (size_t)r0 * 768 + colbase + nt * 8 + tig * 2;
                *(__half2*)&C[gc]           = __floats2half2_rn(acc[mt][nt][0] + bx[nt], acc[mt][nt][1] + by[nt]);
                *(__half2*)&C[gc + 8 * 768] = __floats2half2_rn(acc[mt][nt][2] + bx[nt], acc[mt][nt][3] + by[nt]);
            }
        }
    }
}

// ---------------- K2b: msum per batch ----------------------------------------
__global__ void msum_kernel(const float* __restrict__ am) {
    __shared__ float red[256];
    int b = blockIdx.x;
    float s = 0.0f;
    for (int i = threadIdx.x; i < Ss; i += 256)
        s += (am[b * Ss + i] != 0.0f) ? 0.0f : 1.0f;
    red[threadIdx.x] = s;
    __syncthreads();
    for (int o = 128; o; o >>= 1) {
        if (threadIdx.x < o) red[threadIdx.x] += red[threadIdx.x + o];
        __syncthreads();
    }
    if (threadIdx.x == 0) g_red[MSUM_OFF + b] = red[0];
}

// ---------------- K3: kv = K^T V (+ ksum, vsum) via HMMA ----------------------
__global__ void __launch_bounds__(160) kv_mma() {
    __shared__ __half Ks[2][64 * 64];
    __shared__ __half Vs[2][64 * 64];

    const int bh = blockIdx.x, sc = blockIdx.y;
    const int b = bh / NH, h = bh % NH;
    const int t = threadIdx.x;
    const int wid = t >> 5, lane = t & 31;
    const int grp = lane >> 2, tig = lane & 3;
    const uint32_t sK = smem_u32(Ks);
    const uint32_t sV = smem_u32(Vs);
    const int s_base = sc * 512;

    auto load_tile = [&](int tile, int buf) {
        int s0 = s_base + tile * 64;
        for (int i = t; i < 1024; i += 160) {
            int isV = i >> 9;
            int j = i & 511;
            int row = j >> 3, ch = j & 7;
            uint32_t off = SWZ((uint32_t)(row * 128 + ch * 16));
            const __half* src = (isV ? g_Vh : g_Kh)
                + ((size_t)(b * Ss + s0 + row)) * 768 + h * 64 + ch * 8;
            CP_ASYNC16((isV ? sV : sK) + buf * 8192 + off, src);
        }
        CP_COMMIT();
    };

    float acc[9][4];
    #pragma unroll
    for (int j = 0; j < 9; j++)
        #pragma unroll
        for (int c = 0; c < 4; c++) acc[j][c] = 0.0f;

    uint32_t a_ones[4];
    a_ones[0] = (grp == 0) ? ONES2 : 0u;
    a_ones[1] = 0u;
    a_ones[2] = (grp == 0) ? ONES2 : 0u;
    a_ones[3] = 0u;
    uint32_t b_ones[2];
    b_ones[0] = (grp == 0) ? ONES2 : 0u;
    b_ones[1] = (grp == 0) ? ONES2 : 0u;

    load_tile(0, 0);

    for (int tile = 0; tile < 8; tile++) {
        const int buf = tile & 1;
        if (tile + 1 < 8) {
            load_tile(tile + 1, buf ^ 1);
            asm volatile("cp.async.wait_group 1;" ::: "memory");
        } else {
            asm volatile("cp.async.wait_group 0;" ::: "memory");
        }
        __syncthreads();

        const uint32_t Kb = sK + buf * 8192;
        const uint32_t Vb = sV + buf * 8192;

        #pragma unroll
        for (int ks = 0; ks < 4; ks++) {
            uint32_t afr[4];
            if (wid < 4) {
                int row = ks * 16 + ((lane >> 4) << 3) + (lane & 7);
                LDMATRIX_X4_T(afr, Kb + SWZ((uint32_t)(row * 128 + wid * 32 + ((lane >> 3) & 1) * 16)));
            } else {
                afr[0] = a_ones[0]; afr[1] = a_ones[1];
                afr[2] = a_ones[2]; afr[3] = a_ones[3];
            }
            uint32_t bfr[4][4];
            #pragma unroll
            for (int bp = 0; bp < 4; bp++) {
                int row = ks * 16 + (((lane >> 3) & 1) << 3) + (lane & 7);
                LDMATRIX_X4_T(bfr[bp], Vb + SWZ((uint32_t)(row * 128 + bp * 32 + (lane >> 4) * 16)));
            }
            #pragma unroll
            for (int nt = 0; nt < 8; nt++)
                mma_f16(acc[nt], afr, &bfr[nt >> 1][(nt & 1) * 2]);
            mma_f16(acc[8], afr, b_ones);
        }
        __syncthreads();
    }

    float* kvb = g_red + KV_OFF + bh * 4096;
    if (wid < 4) {
        int d = wid * 16 + grp;
        #pragma unroll
        for (int nt = 0; nt < 8; nt++) {
            int e = nt * 8 + tig * 2;
            atomicAdd(&kvb[d * 64 + e],           acc[nt][0]);
            atomicAdd(&kvb[d * 64 + e + 1],       acc[nt][1]);
            atomicAdd(&kvb[(d + 8) * 64 + e],     acc[nt][2]);
            atomicAdd(&kvb[(d + 8) * 64 + e + 1], acc[nt][3]);
        }
        if (tig == 0) {
            atomicAdd(&g_red[KSUM_OFF + bh * 64 + d],     acc[8][0]);
            atomicAdd(&g_red[KSUM_OFF + bh * 64 + d + 8], acc[8][2]);
        }
    } else if (grp == 0) {
        #pragma unroll
        for (int nt = 0; nt < 8; nt++) {
            int e = nt * 8 + tig * 2;
            atomicAdd(&g_red[VSUM_OFF + bh * 64 + e],     acc[nt][0]);
            atomicAdd(&g_red[VSUM_OFF + bh * 64 + e + 1], acc[nt][1]);
        }
    }
}

// ---------------- K4: out via fp16 HMMA, 4 q-tiles per CTA --------------------
__global__ void __launch_bounds__(128) out_mma(float* __restrict__ out) {
    __shared__ __half Qs[2][128 * 64];
    __shared__ __half kvT[80 * 64];
    __shared__ float nqs[128];
    __shared__ float vsm[64];

    const int bh = blockIdx.x, sc = blockIdx.y;
    const int b = bh / NH, h = bh % NH;
    const int t = threadIdx.x;
    const int wid = t >> 5, lane = t & 31;
    const int grp = lane >> 2, tig = lane & 3;
    const uint32_t sQ = smem_u32(Qs);
    const uint32_t sT = smem_u32(kvT);

    auto load_q = [&](int st2, int buf) {
        int s0 = sc * 512 + st2 * 128;
        #pragma unroll
        for (int i = 0; i < 8; i++) {
            int s = t + i * 128;
            int row = s >> 3, ch = s & 7;
            CP_ASYNC16(sQ + buf * 16384 + SWZ((uint32_t)(row * 128 + ch * 16)),
                       g_Qh + ((size_t)(b * Ss + s0 + row)) * 768 + h * 64 + ch * 8);
        }
        CP_COMMIT();
    };

    load_q(0, 0);

    for (int idx = t; idx < 80 * 64; idx += 128) {
        int n = idx >> 6, k = idx & 63;
        float v;
        if (n < 64)       v = g_red[KV_OFF + bh * 4096 + k * 64 + n];
        else if (n == 64) v = g_red[KSUM_OFF + bh * 64 + k];
        else              v = 0.0f;
        *(__half*)((char*)kvT + SWZ((uint32_t)(n * 128 + k * 2))) = __float2half_rn(v);
    }
    if (t < 64) vsm[t] = g_red[VSUM_OFF + bh * 64 + t];
    const float msum = g_red[MSUM_OFF + b];

    for (int st2 = 0; st2 < 4; st2++) {
        const int buf = st2 & 1;
        if (st2 + 1 < 4) {
            load_q(st2 + 1, buf ^ 1);
            asm volatile("cp.async.wait_group 1;" ::: "memory");
        } else {
            asm volatile("cp.async.wait_group 0;" ::: "memory");
        }
        __syncthreads();

        const uint32_t Qb = sQ + buf * 16384;

        float acc[2][9][4];
        #pragma unroll
        for (int i = 0; i < 2; i++)
            #pragma unroll
            for (int j = 0; j < 9; j++)
                #pragma unroll
                for (int c = 0; c < 4; c++) acc[i][j][c] = 0.0f;

        #pragma unroll
        for (int ks = 0; ks < 4; ks++) {
            const int k0b = ks * 32;
            uint32_t afr[2][4];
            #pragma unroll
            for (int mt = 0; mt < 2; mt++) {
                int row = wid * 32 + mt * 16 + (lane & 15);
                LDMATRIX_X4(afr[mt], Qb + SWZ((uint32_t)(row * 128 + k0b + (lane >> 4) * 16)));
            }
            uint32_t bfr[5][4];
            #pragma unroll
            for (int bp = 0; bp < 5; bp++) {
                int row = bp * 16 + (lane & 7) + ((lane >> 4) << 3);
                LDMATRIX_X4(bfr[bp], sT + SWZ((uint32_t)(row * 128 + k0b + ((lane >> 3) & 1) * 16)));
            }
            #pragma unroll
            for (int mt = 0; mt < 2; mt++)
                #pragma unroll
                for (int nt = 0; nt < 9; nt++)
                    mma_f16(acc[mt][nt], afr[mt], &bfr[nt >> 1][(nt & 1) * 2]);
        }

        if (tig == 0) {
            #pragma unroll
            for (int mt = 0; mt < 2; mt++) {
                nqs[wid * 32 + mt * 16 + grp]     = acc[mt][8][0];
                nqs[wid * 32 + mt * 16 + grp + 8] = acc[mt][8][2];
            }
        }
        __syncthreads();

        const int srow = sc * 512 + st2 * 128;
        #pragma unroll
        for (int mt = 0; mt < 2; mt++) {
            int r0 = wid * 32 + mt * 16 + grp;
            float inv0 = 1.0f / (nqs[r0]     + EPS + msum);
            float inv1 = 1.0f / (nqs[r0 + 8] + EPS + msum);
            size_t g0 = ((size_t)(b * Ss + srow + r0))     * HID + h * HD;
            size_t g1 = ((size_t)(b * Ss + srow + r0 + 8)) * HID + h * HD;
            #pragma unroll
            for (int nt = 0; nt < 8; nt++) {
                int col = nt * 8 + tig * 2;
                float vx = vsm[col], vy = vsm[col + 1];
                float2 o0 = make_float2((acc[mt][nt][0] + vx) * inv0, (acc[mt][nt][1] + vy) * inv0);
                float2 o1 = make_float2((acc[mt][nt][2] + vx) * inv1, (acc[mt][nt][3] + vy) * inv1);
                *(float2*)&out[g0 + col] = o0;
                *(float2*)&out[g1 + col] = o1;
            }
        }
    }
}

// ---------------- launch ------------------------------------------------------
typedef CUresult (CUDAAPI *PFN_encodeTiled)(
    CUtensorMap*, CUtensorMapDataType, cuuint32_t, void*,
    const cuuint64_t*, const cuuint64_t*, const cuuint32_t*, const cuuint32_t*,
    CUtensorMapInterleave, CUtensorMapSwizzle, CUtensorMapL2promotion,
    CUtensorMapFloatOOBfill);

extern "C" void kernel_launch(void* const* d_in, const int* in_sizes, int n_in,
                              void* d_out, int out_size)
{
    const float* X  = (const float*)d_in[0];
    const float* am = (const float*)d_in[1];
    const float* Wq = (const float*)d_in[2];
    const float* bq = (const float*)d_in[3];
    const float* Wk = (const float*)d_in[4];
    const float* bk = (const float*)d_in[5];
    const float* Wv = (const float*)d_in[6];
    const float* bv = (const float*)d_in[7];
    float* out = (float*)d_out;

    // tensor maps for the GEMM's TMA loads (host-side encode; no device alloc)
    void* encFn = nullptr;
    cudaDriverEntryPointQueryResult qr;
    cudaGetDriverEntryPointByVersion("cuTensorMapEncodeTiled", &encFn, 12000,
                                     cudaEnableDefault, &qr);
    PFN_encodeTiled encode = (PFN_encodeTiled)encFn;

    void *pX = nullptr, *pW = nullptr;
    cudaGetSymbolAddress(&pX, g_Xh);
    cudaGetSymbolAddress(&pW, g_Wh);

    CUtensorMap tmX, tmW;
    {
        cuuint64_t dims[2]    = {768, (cuuint64_t)ROWS};
        cuuint64_t stride[1]  = {768 * sizeof(__half)};
        cuuint32_t box[2]     = {64, 128};
        cuuint32_t estr[2]    = {1, 1};
        encode(&tmX, CU_TENSOR_MAP_DATA_TYPE_FLOAT16, 2, pX, dims, stride, box, estr,
               CU_TENSOR_MAP_INTERLEAVE_NONE, CU_TENSOR_MAP_SWIZZLE_128B,
               CU_TENSOR_MAP_L2_PROMOTION_L2_128B, CU_TENSOR_MAP_FLOAT_OOB_FILL_NONE);
        cuuint64_t dimsW[2]   = {768, 3 * HID};
        encode(&tmW, CU_TENSOR_MAP_DATA_TYPE_FLOAT16, 2, pW, dimsW, stride, box, estr,
               CU_TENSOR_MAP_INTERLEAVE_NONE, CU_TENSOR_MAP_SWIZZLE_128B,
               CU_TENSOR_MAP_L2_PROMOTION_L2_128B, CU_TENSOR_MAP_FLOAT_OOB_FILL_NONE);
    }

    cudaFuncSetAttribute(gemm_qkv_h, cudaFuncAttributeMaxDynamicSharedMemorySize, GK_SMEM);

    // gemm stays the 4th launch for ncu capture
    convX_kernel<<<(ROWS * HID / 4) / 256, 256>>>(X);                      // 1
    convW_kernel<<<WBLKS + ZBLKS, 256>>>(Wq, Wk, Wv);                      // 2 (conv + zero)
    msum_kernel<<<Bb, 256>>>(am);                                          // 3

    dim3 g1(18, 256);
    gemm_qkv_h<<<g1, 128, GK_SMEM>>>(tmX, tmW, am, bq, bk, bv);            // 4

    dim3 g3(48, 16);
    kv_mma<<<g3, 160>>>();                                                 // 5

    dim3 g4(48, 16);
    out_mma<<<g4, 128>>>(out);                                             // 6
}

// round 15
// speedup vs baseline: 1.5942x; 1.0065x over previous
#include <cuda_runtime.h>
#include <cuda_fp16.h>
#include <cuda.h>
#include <cstdint>

// Problem constants
#define Bb   4
#define Ss   8192
#define HID  768
#define NH   12
#define HD   64
#define ROWS (Bb*Ss)          // 32768
#define EPS  1e-5f

// ---------------- scratch (device globals; no allocations allowed) ----------
__device__ __half g_Qh[(size_t)ROWS * HID];
__device__ __half g_Kh[(size_t)ROWS * HID];
__device__ __half g_Vh[(size_t)ROWS * HID];
__device__ __half g_Xh[(size_t)ROWS * HID];          // fp16 copy of X
__device__ __half g_Wh[(size_t)3 * HID * HID];       // fp16 [Wq;Wk;Wv]

#define KV_OFF   0                       // 48 * 64 * 64 = 196608
#define KSUM_OFF (48*4096)
#define VSUM_OFF (KSUM_OFF + 48*64)
#define MSUM_OFF (VSUM_OFF + 48*64)
#define RED_TOTAL (MSUM_OFF + 4)         // 202756 floats
#define RED_N4    ((RED_TOTAL + 3) / 4)
__device__ float g_red[RED_N4 * 4];

// ================= helpers ====================================================
__device__ __forceinline__ uint32_t smem_u32(const void* p) {
    uint32_t a;
    asm("{ .reg .u64 t; cvta.to.shared.u64 t, %1; cvt.u32.u64 %0, t; }" : "=r"(a) : "l"(p));
    return a;
}
#define CP_ASYNC16(dst, src) \
    asm volatile("cp.async.cg.shared.global [%0], [%1], 16;" :: "r"((uint32_t)(dst)), "l"(src) : "memory")
#define CP_COMMIT() asm volatile("cp.async.commit_group;" ::: "memory")
#define SWZ(o) ((o) ^ (((o) >> 3) & 0x70))

__device__ __forceinline__ void mma_f16(float* d, const uint32_t* a, const uint32_t* b) {
    asm volatile(
        "mma.sync.aligned.m16n8k16.row.col.f32.f16.f16.f32 "
        "{%0,%1,%2,%3}, {%4,%5,%6,%7}, {%8,%9}, {%0,%1,%2,%3};"
        : "+f"(d[0]), "+f"(d[1]), "+f"(d[2]), "+f"(d[3])
        : "r"(a[0]), "r"(a[1]), "r"(a[2]), "r"(a[3]), "r"(b[0]), "r"(b[1]));
}
#define LDMATRIX_X4(r, addr) \
    asm volatile("ldmatrix.sync.aligned.m8n8.x4.shared.b16 {%0,%1,%2,%3}, [%4];" \
        : "=r"((r)[0]), "=r"((r)[1]), "=r"((r)[2]), "=r"((r)[3]) : "r"(addr))
#define LDMATRIX_X4_T(r, addr) \
    asm volatile("ldmatrix.sync.aligned.m8n8.x4.trans.shared.b16 {%0,%1,%2,%3}, [%4];" \
        : "=r"((r)[0]), "=r"((r)[1]), "=r"((r)[2]), "=r"((r)[3]) : "r"(addr))
#define ONES2 0x3C003C00u   // half2(1.0, 1.0)

#define MBARRIER_INIT(mbar, cnt) \
    asm volatile("mbarrier.init.shared.b64 [%0], %1;" :: "r"((uint32_t)(mbar)), "r"((uint32_t)(cnt)) : "memory")
#define MBARRIER_EXPECT_TX(mbar, bytes) \
    asm volatile("mbarrier.arrive.expect_tx.shared.b64 _, [%0], %1;" :: "r"((uint32_t)(mbar)), "r"((uint32_t)(bytes)) : "memory")
#define MBARRIER_WAIT_PARITY(mbar, parity) do { \
    uint32_t _m = (uint32_t)(mbar); uint32_t _p = (uint32_t)(parity); uint32_t _d; \
    asm volatile("{\n\t.reg .pred p;\n\t" \
        "mbarrier.try_wait.parity.acquire.cta.shared::cta.b64 p, [%1], %2;\n\t" \
        "selp.b32 %0, 1, 0, p;\n\t}" : "=r"(_d) : "r"(_m), "r"(_p) : "memory"); \
    if (!_d) { \
        asm volatile("{\n\t.reg .pred P1;\n\t" \
            "WL_%=:\n\t" \
            "mbarrier.try_wait.parity.acquire.cta.shared::cta.b64 P1, [%0], %1, 0x989680;\n\t" \
            "@P1 bra.uni WD_%=;\n\t" \
            "bra.uni WL_%=;\n\t" \
            "WD_%=:\n\t}" :: "r"(_m), "r"(_p) : "memory"); \
    } } while(0)
#define TMA_LOAD_2D(smem_addr, tmap_ptr, cx, cy, mbar) \
    asm volatile("cp.async.bulk.tensor.2d.shared::cta.global.tile.mbarrier::complete_tx::bytes " \
        "[%0], [%1, {%2, %3}], [%4];" \
        :: "r"((uint32_t)(smem_addr)), "l"(tmap_ptr), "r"((int)(cx)), "r"((int)(cy)), \
           "r"((uint32_t)(mbar)) : "memory")

// ---------------- K-1a: fp32 -> fp16 converter for X ---------------------------
__global__ void convX_kernel(const float* __restrict__ X) {
    size_t i = (size_t)blockIdx.x * 256 + threadIdx.x;
    float4 v = ((const float4*)X)[i];
    ((__half2*)g_Xh)[2*i]   = __floats2half2_rn(v.x, v.y);
    ((__half2*)g_Xh)[2*i+1] = __floats2half2_rn(v.z, v.w);
}

// ---------------- K-1b: converter for W + zero of g_red (fused) ---------------
#define WBLKS 1728
#define ZBLKS ((RED_N4 + 255) / 256)
__global__ void convW_kernel(const float* __restrict__ Wq,
                             const float* __restrict__ Wk,
                             const float* __restrict__ Wv) {
    if (blockIdx.x >= WBLKS) {
        size_t z = (size_t)(blockIdx.x - WBLKS) * 256 + threadIdx.x;
        if (z < RED_N4) ((float4*)g_red)[z] = make_float4(0.f, 0.f, 0.f, 0.f);
        return;
    }
    size_t i = (size_t)blockIdx.x * 256 + threadIdx.x;
    const size_t per = (size_t)HID * HID / 4;
    const float* src = (i < per) ? Wq : (i < 2*per) ? Wk : Wv;
    size_t j = i % per;
    float4 v = ((const float4*)src)[j];
    ((__half2*)g_Wh)[2*i]   = __floats2half2_rn(v.x, v.y);
    ((__half2*)g_Wh)[2*i+1] = __floats2half2_rn(v.z, v.w);
}

// ---------------- K1: fused QKV projection (fp16 HMMA, TMA loads) -------------
// C = X[32768,768] @ W^T. CTA tile 128x128x64, 4 warps (2m x 2n), warp 64x64.
// 3 TMA stages; TWO kt per __syncthreads: wait/compute(2p), wait/compute(2p+1),
// sync, then issue loads 2p+3, 2p+4 into the two stages the barrier just freed.
#define GK_SMEM (6 * 16384 + 64)   // A 3x16KB + B 3x16KB + mbarriers

__global__ void __launch_bounds__(128, 2) gemm_qkv_h(
    const __grid_constant__ CUtensorMap tmX,
    const __grid_constant__ CUtensorMap tmW,
    const float* __restrict__ am,
    const float* __restrict__ bq, const float* __restrict__ bk, const float* __restrict__ bv)
{
    extern __shared__ char smem[];
    const uint32_t sb = smem_u32(smem);
    const uint32_t mb = sb + 98304;      // full[3]

    const int t    = threadIdx.x;
    const int wid  = t >> 5, lane = t & 31;
    const int wm   = wid & 1;           // 2 warps in m
    const int wn   = wid >> 1;          // 2 warps in n
    const int grp  = lane >> 2, tig = lane & 3;

    const int nb = blockIdx.x;          // 0..17
    const int mbk = blockIdx.y;         // 0..255
    const int mat = nb / 6;             // 0=q 1=k 2=v
    const float* bias = (mat == 0) ? bq : (mat == 1) ? bk : bv;
    __half* C         = (mat == 0) ? g_Qh : (mat == 1) ? g_Kh : g_Vh;
    const int n0 = (nb % 6) * 128;
    const int m0 = mbk * 128;
    const int wrow0 = nb * 128;         // row base within g_Wh [2304, 768]

    if (t == 0) {
        MBARRIER_INIT(mb + 0, 1);
        MBARRIER_INIT(mb + 8, 1);
        MBARRIER_INIT(mb + 16, 1);
        asm volatile("fence.proxy.async.shared::cta;" ::: "memory");
    }
    __syncthreads();

    auto issue = [&](int j, int stg) {   // t==0 only
        uint32_t bar = mb + stg * 8;
        MBARRIER_EXPECT_TX(bar, 32768u);
        TMA_LOAD_2D(sb + stg * 16384,         &tmX, j * 64, m0,    bar);
        TMA_LOAD_2D(sb + 49152 + stg * 16384, &tmW, j * 64, wrow0, bar);
    };

    float acc[4][8][4];
    #pragma unroll
    for (int i = 0; i < 4; i++)
        #pragma unroll
        for (int j = 0; j < 8; j++)
            #pragma unroll
            for (int c = 0; c < 4; c++) acc[i][j][c] = 0.0f;

    if (t == 0) { issue(0, 0); issue(1, 1); issue(2, 2); }

    auto compute_kt = [&](int kt) {
        const int buf = kt % 3;
        const uint32_t Abase = sb + buf * 16384;
        const uint32_t Bbase = sb + 49152 + buf * 16384;
        #pragma unroll
        for (int ks = 0; ks < 4; ks++) {
            const int k0b = ks * 32;
            uint32_t bfr[4][4];
            #pragma unroll
            for (int bp = 0; bp < 4; bp++) {
                int row = wn * 64 + bp * 16 + (lane & 7) + ((lane >> 4) << 3);
                LDMATRIX_X4(bfr[bp], Bbase + SWZ((uint32_t)(row * 128 + k0b + ((lane >> 3) & 1) * 16)));
            }
            #pragma unroll
            for (int mt = 0; mt < 4; mt++) {
                uint32_t afr[4];
                int row = wm * 64 + mt * 16 + (lane & 15);
                LDMATRIX_X4(afr, Abase + SWZ((uint32_t)(row * 128 + k0b + (lane >> 4) * 16)));
                #pragma unroll
                for (int nt = 0; nt < 8; nt++)
                    mma_f16(acc[mt][nt], afr, &bfr[nt >> 1][(nt & 1) * 2]);
            }
        }
    };

    for (int p = 0; p < 6; p++) {
        const int k0 = 2 * p, k1 = 2 * p + 1;
        MBARRIER_WAIT_PARITY(mb + (k0 % 3) * 8, (k0 / 3) & 1);
        compute_kt(k0);
        MBARRIER_WAIT_PARITY(mb + (k1 % 3) * 8, (k1 / 3) & 1);
        compute_kt(k1);
        __syncthreads();   // all warps done with stages k0%3 and k1%3
        if (t == 0) {
            if (k0 + 3 < 12) issue(k0 + 3, (k0 + 3) % 3);  // == stage k0%3
            if (k1 + 3 < 12) issue(k1 + 3, (k1 + 3) % 3);  // == stage k1%3
        }
    }

    // -------- epilogue (warp-local: this warp's 64 cols = one head) --------
    const int colbase = n0 + wn * 64;
    float bx[8], by[8];
    #pragma unroll
    for (int nt = 0; nt < 8; nt++) {
        bx[nt] = bias[colbase + nt * 8 + tig * 2];
        by[nt] = bias[colbase + nt * 8 + tig * 2 + 1];
    }

    if (mat < 2) {
        #pragma unroll
        for (int mt = 0; mt < 4; mt++) {
            const int r0 = m0 + wm * 64 + mt * 16 + grp;
            const float mr0 = (am[r0]     != 0.0f) ? 0.0f : 1.0f;
            const float mr1 = (am[r0 + 8] != 0.0f) ? 0.0f : 1.0f;
            float ssq0 = 0.0f, ssq1 = 0.0f;
            #pragma unroll
            for (int nt = 0; nt < 8; nt++) {
                float a0 = (acc[mt][nt][0] + bx[nt]) * mr0;
                float a1 = (acc[mt][nt][1] + by[nt]) * mr0;
                float a2 = (acc[mt][nt][2] + bx[nt]) * mr1;
                float a3 = (acc[mt][nt][3] + by[nt]) * mr1;
                acc[mt][nt][0] = a0; acc[mt][nt][1] = a1;
                acc[mt][nt][2] = a2; acc[mt][nt][3] = a3;
                ssq0 += a0*a0 + a1*a1;
                ssq1 += a2*a2 + a3*a3;
            }
            #pragma unroll
            for (int off = 1; off <= 2; off <<= 1) {
                ssq0 += __shfl_xor_sync(0xffffffffu, ssq0, off);
                ssq1 += __shfl_xor_sync(0xffffffffu, ssq1, off);
            }
            const float inv0 = 1.0f / (sqrtf(ssq0) + EPS);
            const float inv1 = 1.0f / (sqrtf(ssq1) + EPS);
            #pragma unroll
            for (int nt = 0; nt < 8; nt++) {
                size_t gc = (size_t)r0 * 768 + colbase + nt * 8 + tig * 2;
                *(__half2*)&C[gc]           = __floats2half2_rn(acc[mt][nt][0] * inv0, acc[mt][nt][1] * inv0);
                *(__half2*)&C[gc + 8 * 768] = __floats2half2_rn(acc[mt][nt][2] * inv1, acc[mt][nt][3] * inv1);
            }
        }
    } else {
        #pragma unroll
        for (int mt = 0; mt < 4; mt++) {
            const int r0 = m0 + wm * 64 + mt * 16 + grp;
            #pragma unroll
            for (int nt = 0; nt < 8; nt++) {
                size_t gc = (size_t)r0 * 768 + colbase + nt * 8 + tig * 2;
                *(__half2*)&C[gc]           = __floats2half2_rn(acc[mt][nt][0] + bx[nt], acc[mt][nt][1] + by[nt]);
                *(__half2*)&C[gc + 8 * 768] = __floats2half2_rn(acc[mt][nt][2] + bx[nt], acc[mt][nt][3] + by[nt]);
            }
        }
    }
}

// ---------------- K2b: msum per batch ----------------------------------------
__global__ void msum_kernel(const float* __restrict__ am) {
    __shared__ float red[256];
    int b = blockIdx.x;
    float s = 0.0f;
    for (int i = threadIdx.x; i < Ss; i += 256)
        s += (am[b * Ss + i] != 0.0f) ? 0.0f : 1.0f;
    red[threadIdx.x] = s;
    __syncthreads();
    for (int o = 128; o; o >>= 1) {
        if (threadIdx.x < o) red[threadIdx.x] += red[threadIdx.x + o];
        __syncthreads();
    }
    if (threadIdx.x == 0) g_red[MSUM_OFF + b] = red[0];
}

// ---------------- K3: kv = K^T V (+ ksum, vsum) via HMMA ----------------------
__global__ void __launch_bounds__(160) kv_mma() {
    __shared__ __half Ks[2][64 * 64];
    __shared__ __half Vs[2][64 * 64];

    const int bh = blockIdx.x, sc = blockIdx.y;
    const int b = bh / NH, h = bh % NH;
    const int t = threadIdx.x;
    const int wid = t >> 5, lane = t & 31;
    const int grp = lane >> 2, tig = lane & 3;
    const uint32_t sK = smem_u32(Ks);
    const uint32_t sV = smem_u32(Vs);
    const int s_base = sc * 512;

    auto load_tile = [&](int tile, int buf) {
        int s0 = s_base + tile * 64;
        for (int i = t; i < 1024; i += 160) {
            int isV = i >> 9;
            int j = i & 511;
            int row = j >> 3, ch = j & 7;
            uint32_t off = SWZ((uint32_t)(row * 128 + ch * 16));
            const __half* src = (isV ? g_Vh : g_Kh)
                + ((size_t)(b * Ss + s0 + row)) * 768 + h * 64 + ch * 8;
            CP_ASYNC16((isV ? sV : sK) + buf * 8192 + off, src);
        }
        CP_COMMIT();
    };

    float acc[9][4];
    #pragma unroll
    for (int j = 0; j < 9; j++)
        #pragma unroll
        for (int c = 0; c < 4; c++) acc[j][c] = 0.0f;

    uint32_t a_ones[4];
    a_ones[0] = (grp == 0) ? ONES2 : 0u;
    a_ones[1] = 0u;
    a_ones[2] = (grp == 0) ? ONES2 : 0u;
    a_ones[3] = 0u;
    uint32_t b_ones[2];
    b_ones[0] = (grp == 0) ? ONES2 : 0u;
    b_ones[1] = (grp == 0) ? ONES2 : 0u;

    load_tile(0, 0);

    for (int tile = 0; tile < 8; tile++) {
        const int buf = tile & 1;
        if (tile + 1 < 8) {
            load_tile(tile + 1, buf ^ 1);
            asm volatile("cp.async.wait_group 1;" ::: "memory");
        } else {
            asm volatile("cp.async.wait_group 0;" ::: "memory");
        }
        __syncthreads();

        const uint32_t Kb = sK + buf * 8192;
        const uint32_t Vb = sV + buf * 8192;

        #pragma unroll
        for (int ks = 0; ks < 4; ks++) {
            uint32_t afr[4];
            if (wid < 4) {
                int row = ks * 16 + ((lane >> 4) << 3) + (lane & 7);
                LDMATRIX_X4_T(afr, Kb + SWZ((uint32_t)(row * 128 + wid * 32 + ((lane >> 3) & 1) * 16)));
            } else {
                afr[0] = a_ones[0]; afr[1] = a_ones[1];
                afr[2] = a_ones[2]; afr[3] = a_ones[3];
            }
            uint32_t bfr[4][4];
            #pragma unroll
            for (int bp = 0; bp < 4; bp++) {
                int row = ks * 16 + (((lane >> 3) & 1) << 3) + (lane & 7);
                LDMATRIX_X4_T(bfr[bp], Vb + SWZ((uint32_t)(row * 128 + bp * 32 + (lane >> 4) * 16)));
            }
            #pragma unroll
            for (int nt = 0; nt < 8; nt++)
                mma_f16(acc[nt], afr, &bfr[nt >> 1][(nt & 1) * 2]);
            mma_f16(acc[8], afr, b_ones);
        }
        __syncthreads();
    }

    float* kvb = g_red + KV_OFF + bh * 4096;
    if (wid < 4) {
        int d = wid * 16 + grp;
        #pragma unroll
        for (int nt = 0; nt < 8; nt++) {
            int e = nt * 8 + tig * 2;
            atomicAdd(&kvb[d * 64 + e],           acc[nt][0]);
            atomicAdd(&kvb[d * 64 + e + 1],       acc[nt][1]);
            atomicAdd(&kvb[(d + 8) * 64 + e],     acc[nt][2]);
            atomicAdd(&kvb[(d + 8) * 64 + e + 1], acc[nt][3]);
        }
        if (tig == 0) {
            atomicAdd(&g_red[KSUM_OFF + bh * 64 + d],     acc[8][0]);
            atomicAdd(&g_red[KSUM_OFF + bh * 64 + d + 8], acc[8][2]);
        }
    } else if (grp == 0) {
        #pragma unroll
        for (int nt = 0; nt < 8; nt++) {
            int e = nt * 8 + tig * 2;
            atomicAdd(&g_red[VSUM_OFF + bh * 64 + e],     acc[nt][0]);
            atomicAdd(&g_red[VSUM_OFF + bh * 64 + e + 1], acc[nt][1]);
        }
    }
}

// ---------------- K4: out via fp16 HMMA, 4 q-tiles per CTA --------------------
__global__ void __launch_bounds__(128) out_mma(float* __restrict__ out) {
    __shared__ __half Qs[2][128 * 64];
    __shared__ __half kvT[80 * 64];
    __shared__ float nqs[128];
    __shared__ float vsm[64];

    const int bh = blockIdx.x, sc = blockIdx.y;
    const int b = bh / NH, h = bh % NH;
    const int t = threadIdx.x;
    const int wid = t >> 5, lane = t & 31;
    const int grp = lane >> 2, tig = lane & 3;
    const uint32_t sQ = smem_u32(Qs);
    const uint32_t sT = smem_u32(kvT);

    auto load_q = [&](int st2, int buf) {
        int s0 = sc * 512 + st2 * 128;
        #pragma unroll
        for (int i = 0; i < 8; i++) {
            int s = t + i * 128;
            int row = s >> 3, ch = s & 7;
            CP_ASYNC16(sQ + buf * 16384 + SWZ((uint32_t)(row * 128 + ch * 16)),
                       g_Qh + ((size_t)(b * Ss + s0 + row)) * 768 + h * 64 + ch * 8);
        }
        CP_COMMIT();
    };

    load_q(0, 0);

    for (int idx = t; idx < 80 * 64; idx += 128) {
        int n = idx >> 6, k = idx & 63;
        float v;
        if (n < 64)       v = g_red[KV_OFF + bh * 4096 + k * 64 + n];
        else if (n == 64) v = g_red[KSUM_OFF + bh * 64 + k];
        else              v = 0.0f;
        *(__half*)((char*)kvT + SWZ((uint32_t)(n * 128 + k * 2))) = __float2half_rn(v);
    }
    if (t < 64) vsm[t] = g_red[VSUM_OFF + bh * 64 + t];
    const float msum = g_red[MSUM_OFF + b];

    for (int st2 = 0; st2 < 4; st2++) {
        const int buf = st2 & 1;
        if (st2 + 1 < 4) {
            load_q(st2 + 1, buf ^ 1);
            asm volatile("cp.async.wait_group 1;" ::: "memory");
        } else {
            asm volatile("cp.async.wait_group 0;" ::: "memory");
        }
        __syncthreads();

        const uint32_t Qb = sQ + buf * 16384;

        float acc[2][9][4];
        #pragma unroll
        for (int i = 0; i < 2; i++)
            #pragma unroll
            for (int j = 0; j < 9; j++)
                #pragma unroll
                for (int c = 0; c < 4; c++) acc[i][j][c] = 0.0f;

        #pragma unroll
        for (int ks = 0; ks < 4; ks++) {
            const int k0b = ks * 32;
            uint32_t afr[2][4];
            #pragma unroll
            for (int mt = 0; mt < 2; mt++) {
                int row = wid * 32 + mt * 16 + (lane & 15);
                LDMATRIX_X4(afr[mt], Qb + SWZ((uint32_t)(row * 128 + k0b + (lane >> 4) * 16)));
            }
            uint32_t bfr[5][4];
            #pragma unroll
            for (int bp = 0; bp < 5; bp++) {
                int row = bp * 16 + (lane & 7) + ((lane >> 4) << 3);
                LDMATRIX_X4(bfr[bp], sT + SWZ((uint32_t)(row * 128 + k0b + ((lane >> 3) & 1) * 16)));
            }
            #pragma unroll
            for (int mt = 0; mt < 2; mt++)
                #pragma unroll
                for (int nt = 0; nt < 9; nt++)
                    mma_f16(acc[mt][nt], afr[mt], &bfr[nt >> 1][(nt & 1) * 2]);
        }

        if (tig == 0) {
            #pragma unroll
            for (int mt = 0; mt < 2; mt++) {
                nqs[wid * 32 + mt * 16 + grp]     = acc[mt][8][0];
                nqs[wid * 32 + mt * 16 + grp + 8] = acc[mt][8][2];
            }
        }
        __syncthreads();

        const int srow = sc * 512 + st2 * 128;
        #pragma unroll
        for (int mt = 0; mt < 2; mt++) {
            int r0 = wid * 32 + mt * 16 + grp;
            float inv0 = 1.0f / (nqs[r0]     + EPS + msum);
            float inv1 = 1.0f / (nqs[r0 + 8] + EPS + msum);
            size_t g0 = ((size_t)(b * Ss + srow + r0))     * HID + h * HD;
            size_t g1 = ((size_t)(b * Ss + srow + r0 + 8)) * HID + h * HD;
            #pragma unroll
            for (int nt = 0; nt < 8; nt++) {
                int col = nt * 8 + tig * 2;
                float vx = vsm[col], vy = vsm[col + 1];
                float2 o0 = make_float2((acc[mt][nt][0] + vx) * inv0, (acc[mt][nt][1] + vy) * inv0);
                float2 o1 = make_float2((acc[mt][nt][2] + vx) * inv1, (acc[mt][nt][3] + vy) * inv1);
                *(float2*)&out[g0 + col] = o0;
                *(float2*)&out[g1 + col] = o1;
            }
        }
    }
}

// ---------------- launch ------------------------------------------------------
typedef CUresult (CUDAAPI *PFN_encodeTiled)(
    CUtensorMap*, CUtensorMapDataType, cuuint32_t, void*,
    const cuuint64_t*, const cuuint64_t*, const cuuint32_t*, const cuuint32_t*,
    CUtensorMapInterleave, CUtensorMapSwizzle, CUtensorMapL2promotion,
    CUtensorMapFloatOOBfill);

extern "C" void kernel_launch(void* const* d_in, const int* in_sizes, int n_in,
                              void* d_out, int out_size)
{
    const float* X  = (const float*)d_in[0];
    const float* am = (const float*)d_in[1];
    const float* Wq = (const float*)d_in[2];
    const float* bq = (const float*)d_in[3];
    const float* Wk = (const float*)d_in[4];
    const float* bk = (const float*)d_in[5];
    const float* Wv = (const float*)d_in[6];
    const float* bv = (const float*)d_in[7];
    float* out = (float*)d_out;

    void* encFn = nullptr;
    cudaDriverEntryPointQueryResult qr;
    cudaGetDriverEntryPointByVersion("cuTensorMapEncodeTiled", &encFn, 12000,
                                     cudaEnableDefault, &qr);
    PFN_encodeTiled encode = (PFN_encodeTiled)encFn;

    void *pX = nullptr, *pW = nullptr;
    cudaGetSymbolAddress(&pX, g_Xh);
    cudaGetSymbolAddress(&pW, g_Wh);

    CUtensorMap tmX, tmW;
    {
        cuuint64_t dims[2]    = {768, (cuuint64_t)ROWS};
        cuuint64_t stride[1]  = {768 * sizeof(__half)};
        cuuint32_t box[2]     = {64, 128};
        cuuint32_t estr[2]    = {1, 1};
        encode(&tmX, CU_TENSOR_MAP_DATA_TYPE_FLOAT16, 2, pX, dims, stride, box, estr,
               CU_TENSOR_MAP_INTERLEAVE_NONE, CU_TENSOR_MAP_SWIZZLE_128B,
               CU_TENSOR_MAP_L2_PROMOTION_L2_128B, CU_TENSOR_MAP_FLOAT_OOB_FILL_NONE);
        cuuint64_t dimsW[2]   = {768, 3 * HID};
        encode(&tmW, CU_TENSOR_MAP_DATA_TYPE_FLOAT16, 2, pW, dimsW, stride, box, estr,
               CU_TENSOR_MAP_INTERLEAVE_NONE, CU_TENSOR_MAP_SWIZZLE_128B,
               CU_TENSOR_MAP_L2_PROMOTION_L2_128B, CU_TENSOR_MAP_FLOAT_OOB_FILL_NONE);
    }

    cudaFuncSetAttribute(gemm_qkv_h, cudaFuncAttributeMaxDynamicSharedMemorySize, GK_SMEM);

    // gemm stays the 4th launch for ncu capture
    convX_kernel<<<(ROWS * HID / 4) / 256, 256>>>(X);                      // 1
    convW_kernel<<<WBLKS + ZBLKS, 256>>>(Wq, Wk, Wv);                      // 2 (conv + zero)
    msum_kernel<<<Bb, 256>>>(am);                                          // 3

    dim3 g1(18, 256);
    gemm_qkv_h<<<g1, 128, GK_SMEM>>>(tmX, tmW, am, bq, bk, bv);            // 4

    dim3 g3(48, 16);
    kv_mma<<<g3, 160>>>();                                                 // 5

    dim3 g4(48, 16);
    out_mma<<<g4, 128>>>(out);                                             // 6
}